// round 2
// baseline (speedup 1.0000x reference)
#include <cuda_runtime.h>
#include <math.h>

#define L6 6
#define BB 32
#define QQ 900
#define DD 256
#define MM (BB*QQ)                 // 28800 tokens per level
#define MD ((size_t)MM*(size_t)DD) // per-level elements

// Scratch (device globals: allocation-free per harness rules)
__device__ float g_x1[(size_t)L6*MM*DD];
__device__ float g_x2[(size_t)L6*MM*DD];
__device__ float g_y1[(size_t)L6*MM*DD];
__device__ float g_y2[(size_t)L6*MM*DD];

__device__ __forceinline__ float warp_sum(float v) {
#pragma unroll
    for (int off = 16; off; off >>= 1)
        v += __shfl_xor_sync(0xffffffffu, v, off);
    return v;
}

// One block computes a 64-row x 256-col output tile (full N => LN can be fused).
// blockIdx.y: 0 = cls path (Linear+LN+ReLU), 1 = reg path (Linear+ReLU)
// blockIdx.z: level
// stage 0: A = hs[l]; stage 1: A = g_x1/g_y1
__global__ __launch_bounds__(256, 2)
void fused_mlp_kernel(int stage,
                      const float* __restrict__ hs,
                      const float* __restrict__ Wc, const float* __restrict__ bc,
                      const float* __restrict__ gc, const float* __restrict__ betac,
                      const float* __restrict__ Wr, const float* __restrict__ br)
{
    const int l    = blockIdx.z;
    const int path = blockIdx.y;
    const int m0   = blockIdx.x * 64;
    const int t    = threadIdx.x;
    const int lane = t & 31, warp = t >> 5;

    const float* A;
    float* O;
    if (stage == 0) {
        A = hs + (size_t)l * MD;                       // hs[l] is [Q*B, D] contiguous, m = q*B+b
        O = (path ? g_y1 : g_x1) + (size_t)l * MD;
    } else {
        A = (path ? g_y1 : g_x1) + (size_t)l * MD;
        O = (path ? g_y2 : g_x2) + (size_t)l * MD;
    }
    const float* W    = (path ? Wr : Wc) + (size_t)l * DD * DD;   // [K,N] row-major
    const float* bias = (path ? br : bc) + l * DD;

    __shared__ float As[32][66];    // [k][m] transposed A tile (66: 8B-aligned rows, pad)
    __shared__ float Bs[32][256];   // [k][n]

    // accumulators: rows paired in f32x2 (p -> rows 2p,2p+1), 8 cols (lane + 32*j)
    unsigned long long acc[4][8];
#pragma unroll
    for (int p = 0; p < 4; ++p)
#pragma unroll
        for (int j = 0; j < 8; ++j) acc[p][j] = 0ull;

    for (int kt = 0; kt < 8; ++kt) {
        // Load A tile 64x32, transpose into As[k][m]
#pragma unroll
        for (int s = 0; s < 2; ++s) {
            int id = t + 256 * s;            // 0..511 float4s
            int r  = id >> 3;                // 0..63
            int c4 = (id & 7) << 2;          // 0..28
            const float4 f = *(const float4*)&A[(size_t)(m0 + r) * DD + kt * 32 + c4];
            As[c4 + 0][r] = f.x;
            As[c4 + 1][r] = f.y;
            As[c4 + 2][r] = f.z;
            As[c4 + 3][r] = f.w;
        }
        // Load B tile 32x256 (direct copy)
#pragma unroll
        for (int s = 0; s < 8; ++s) {
            int id = t + 256 * s;            // 0..2047 float4s
            int kr = id >> 6;                // 0..31
            int c4 = (id & 63) << 2;         // 0..252
            *(float4*)&Bs[kr][c4] = *(const float4*)&W[(size_t)(kt * 32 + kr) * DD + c4];
        }
        __syncthreads();

#pragma unroll 8
        for (int kk = 0; kk < 32; ++kk) {
            unsigned long long a2[4];
#pragma unroll
            for (int p = 0; p < 4; ++p)      // LDS.64 broadcast (all lanes same addr)
                a2[p] = *(const unsigned long long*)&As[kk][warp * 8 + 2 * p];
#pragma unroll
            for (int j = 0; j < 8; ++j) {
                float bj = Bs[kk][lane + 32 * j];   // conflict-free: bank == lane
                unsigned long long b2;
                asm("mov.b64 %0, {%1, %1};" : "=l"(b2) : "f"(bj));
#pragma unroll
                for (int p = 0; p < 4; ++p)
                    asm("fma.rn.f32x2 %0, %1, %2, %0;"
                        : "+l"(acc[p][j]) : "l"(a2[p]), "l"(b2));
            }
        }
        __syncthreads();
    }

    // Unpack accumulators: v[i][j], i = local row, cols = lane + 32*j
    float v[8][8];
#pragma unroll
    for (int p = 0; p < 4; ++p)
#pragma unroll
        for (int j = 0; j < 8; ++j)
            asm("mov.b64 {%0, %1}, %2;"
                : "=f"(v[2 * p][j]), "=f"(v[2 * p + 1][j]) : "l"(acc[p][j]));

    float bv[8];
#pragma unroll
    for (int j = 0; j < 8; ++j) bv[j] = bias[lane + 32 * j];

    if (path == 0) {
        // bias -> LayerNorm (over the 256 cols of each row) -> gamma,beta -> ReLU
        float gv[8], bev[8];
        const float* gp = gc    + l * DD;
        const float* bp = betac + l * DD;
#pragma unroll
        for (int j = 0; j < 8; ++j) { gv[j] = gp[lane + 32 * j]; bev[j] = bp[lane + 32 * j]; }
#pragma unroll
        for (int i = 0; i < 8; ++i) {
            float s1 = 0.f, s2 = 0.f;
#pragma unroll
            for (int j = 0; j < 8; ++j) {
                float x = v[i][j] + bv[j];
                v[i][j] = x;
                s1 += x; s2 += x * x;
            }
            s1 = warp_sum(s1);
            s2 = warp_sum(s2);
            float mean = s1 * (1.0f / 256.0f);
            float var  = s2 * (1.0f / 256.0f) - mean * mean;
            float rs   = rsqrtf(var + 1e-5f);
            float* orow = O + (size_t)(m0 + warp * 8 + i) * DD;
#pragma unroll
            for (int j = 0; j < 8; ++j) {
                float y = (v[i][j] - mean) * rs * gv[j] + bev[j];
                orow[lane + 32 * j] = fmaxf(y, 0.f);
            }
        }
    } else {
        // bias -> ReLU
#pragma unroll
        for (int i = 0; i < 8; ++i) {
            float* orow = O + (size_t)(m0 + warp * 8 + i) * DD;
#pragma unroll
            for (int j = 0; j < 8; ++j)
                orow[lane + 32 * j] = fmaxf(v[i][j] + bv[j], 0.f);
        }
    }
}

// Head: warp per (l, token). cls = x2 @ cw3 + cb3 ; tmp = y2 @ rw3 + rb3 ; coord epilogue.
__global__ __launch_bounds__(256)
void head_kernel(const float* __restrict__ cw3, const float* __restrict__ cb3,
                 const float* __restrict__ rw3, const float* __restrict__ rb3,
                 const float* __restrict__ init_ref, const float* __restrict__ inter_ref,
                 float* __restrict__ out)
{
    __shared__ float Wc[10][256];   // transposed: Wc[c][k]
    __shared__ float Wr[10][256];
    const int t = threadIdx.x, lane = t & 31, warp = t >> 5;
    const int l = blockIdx.x / 3600;                // 3600 blocks per level (28800/8)

    for (int idx = t; idx < 2560; idx += 256) {
        int k = idx / 10, c = idx - k * 10;
        Wc[c][k] = cw3[l * 2560 + idx];
        Wr[c][k] = rw3[l * 2560 + idx];
    }
    __syncthreads();

    const int m = (blockIdx.x % 3600) * 8 + warp;   // token in (q*B+b) order
    const int q = m >> 5, b = m & 31;
    const float* xrow = g_x2 + ((size_t)l * MM + m) * DD;
    const float* yrow = g_y2 + ((size_t)l * MM + m) * DD;

    float xa[10], ya[10];
#pragma unroll
    for (int c = 0; c < 10; ++c) { xa[c] = 0.f; ya[c] = 0.f; }
#pragma unroll
    for (int jj = 0; jj < 8; ++jj) {
        int k = lane + 32 * jj;
        float xv = xrow[k], yv = yrow[k];
#pragma unroll
        for (int c = 0; c < 10; ++c) {
            xa[c] = fmaf(xv, Wc[c][k], xa[c]);
            ya[c] = fmaf(yv, Wr[c][k], ya[c]);
        }
    }
#pragma unroll
    for (int c = 0; c < 10; ++c) { xa[c] = warp_sum(xa[c]); ya[c] = warp_sum(ya[c]); }

    if (lane == 0) {
        const size_t base = (((size_t)l * BB + b) * QQ + q) * 10;
        float tmp[10];
#pragma unroll
        for (int c = 0; c < 10; ++c) {
            out[base + c] = xa[c] + cb3[l * 10 + c];   // cls scores
            tmp[c] = ya[c] + rb3[l * 10 + c];
        }
        const float* rp = (l == 0)
            ? (init_ref + ((size_t)b * QQ + q) * 3)
            : (inter_ref + (((size_t)(l - 1) * BB + b) * QQ + q) * 3);
        float r[3];
#pragma unroll
        for (int i = 0; i < 3; ++i) {
            float x  = fminf(fmaxf(rp[i], 0.f), 1.f);
            float x1 = fmaxf(x, 1e-5f);
            float x2 = fmaxf(1.f - x, 1e-5f);
            r[i] = logf(x1 / x2);                      // inverse sigmoid
        }
        float xy0 = 1.f / (1.f + expf(-(tmp[0] + r[0])));
        float xy1 = 1.f / (1.f + expf(-(tmp[1] + r[1])));
        float z   = 1.f / (1.f + expf(-(tmp[4] + r[2])));
        float* co = out + (size_t)L6 * BB * QQ * 10 + base;   // bbox preds
        co[0] = xy0 * 102.4f - 51.2f;
        co[1] = xy1 * 102.4f - 51.2f;
        co[2] = tmp[2];
        co[3] = tmp[3];
        co[4] = z * 8.0f - 5.0f;
        co[5] = tmp[5]; co[6] = tmp[6]; co[7] = tmp[7]; co[8] = tmp[8]; co[9] = tmp[9];
    }
}

extern "C" void kernel_launch(void* const* d_in, const int* in_sizes, int n_in,
                              void* d_out, int out_size) {
    const float* hs        = (const float*)d_in[0];
    const float* init_ref  = (const float*)d_in[1];
    const float* inter_ref = (const float*)d_in[2];
    const float* cls_w1    = (const float*)d_in[3];
    const float* cls_b1    = (const float*)d_in[4];
    const float* ln1_g     = (const float*)d_in[5];
    const float* ln1_b     = (const float*)d_in[6];
    const float* cls_w2    = (const float*)d_in[7];
    const float* cls_b2    = (const float*)d_in[8];
    const float* ln2_g     = (const float*)d_in[9];
    const float* ln2_b     = (const float*)d_in[10];
    const float* cls_w3    = (const float*)d_in[11];
    const float* cls_b3    = (const float*)d_in[12];
    const float* reg_w1    = (const float*)d_in[13];
    const float* reg_b1    = (const float*)d_in[14];
    const float* reg_w2    = (const float*)d_in[15];
    const float* reg_b2    = (const float*)d_in[16];
    const float* reg_w3    = (const float*)d_in[17];
    const float* reg_b3    = (const float*)d_in[18];
    float* out = (float*)d_out;

    dim3 grid(MM / 64, 2, L6);   // 450 x {cls,reg} x 6 levels
    fused_mlp_kernel<<<grid, 256>>>(0, hs, cls_w1, cls_b1, ln1_g, ln1_b, reg_w1, reg_b1);
    fused_mlp_kernel<<<grid, 256>>>(1, hs, cls_w2, cls_b2, ln2_g, ln2_b, reg_w2, reg_b2);
    head_kernel<<<L6 * (MM / 8), 256>>>(cls_w3, cls_b3, reg_w3, reg_b3,
                                        init_ref, inter_ref, out);
}

// round 3
// speedup vs baseline: 1.0004x; 1.0004x over previous
#include <cuda_runtime.h>
#include <math.h>

#define L6 6
#define BB 32
#define QQ 900
#define DD 256
#define MM (BB*QQ)                 // 28800 tokens per level
#define MD ((size_t)MM*(size_t)DD) // per-level elements

// Scratch (device globals: allocation-free per harness rules)
__device__ float g_x1[(size_t)L6*MM*DD];
__device__ float g_x2[(size_t)L6*MM*DD];
__device__ float g_y1[(size_t)L6*MM*DD];
__device__ float g_y2[(size_t)L6*MM*DD];

__device__ __forceinline__ float warp_sum(float v) {
#pragma unroll
    for (int off = 16; off; off >>= 1)
        v += __shfl_xor_sync(0xffffffffu, v, off);
    return v;
}

// One block computes a 64-row x 256-col output tile (full N => LN can be fused).
// blockIdx.y: 0 = cls path (Linear+LN+ReLU), 1 = reg path (Linear+ReLU)
// blockIdx.z: level
// stage 0: A = hs[l]; stage 1: A = g_x1/g_y1
__global__ __launch_bounds__(256, 2)
void fused_mlp_kernel(int stage,
                      const float* __restrict__ hs,
                      const float* __restrict__ Wc, const float* __restrict__ bc,
                      const float* __restrict__ gc, const float* __restrict__ betac,
                      const float* __restrict__ Wr, const float* __restrict__ br)
{
    const int l    = blockIdx.z;
    const int path = blockIdx.y;
    const int m0   = blockIdx.x * 64;
    const int t    = threadIdx.x;
    const int lane = t & 31, warp = t >> 5;

    const float* A;
    float* O;
    if (stage == 0) {
        A = hs + (size_t)l * MD;                       // hs[l] is [Q*B, D] contiguous, m = q*B+b
        O = (path ? g_y1 : g_x1) + (size_t)l * MD;
    } else {
        A = (path ? g_y1 : g_x1) + (size_t)l * MD;
        O = (path ? g_y2 : g_x2) + (size_t)l * MD;
    }
    const float* W    = (path ? Wr : Wc) + (size_t)l * DD * DD;   // [K,N] row-major
    const float* bias = (path ? br : bc) + l * DD;

    __shared__ float As[32][66];    // [k][m] transposed A tile (66: 8B-aligned rows, pad)
    __shared__ float Bs[32][256];   // [k][n]

    // accumulators: rows paired in f32x2 (p -> rows 2p,2p+1), 8 cols (lane + 32*j)
    unsigned long long acc[4][8];
#pragma unroll
    for (int p = 0; p < 4; ++p)
#pragma unroll
        for (int j = 0; j < 8; ++j) acc[p][j] = 0ull;

    for (int kt = 0; kt < 8; ++kt) {
        // Load A tile 64x32, transpose into As[k][m]
#pragma unroll
        for (int s = 0; s < 2; ++s) {
            int id = t + 256 * s;            // 0..511 float4s
            int r  = id >> 3;                // 0..63
            int c4 = (id & 7) << 2;          // 0..28
            const float4 f = *(const float4*)&A[(size_t)(m0 + r) * DD + kt * 32 + c4];
            As[c4 + 0][r] = f.x;
            As[c4 + 1][r] = f.y;
            As[c4 + 2][r] = f.z;
            As[c4 + 3][r] = f.w;
        }
        // Load B tile 32x256 (direct copy)
#pragma unroll
        for (int s = 0; s < 8; ++s) {
            int id = t + 256 * s;            // 0..2047 float4s
            int kr = id >> 6;                // 0..31
            int c4 = (id & 63) << 2;         // 0..252
            *(float4*)&Bs[kr][c4] = *(const float4*)&W[(size_t)(kt * 32 + kr) * DD + c4];
        }
        __syncthreads();

#pragma unroll 8
        for (int kk = 0; kk < 32; ++kk) {
            unsigned long long a2[4];
#pragma unroll
            for (int p = 0; p < 4; ++p)      // LDS.64 broadcast (all lanes same addr)
                a2[p] = *(const unsigned long long*)&As[kk][warp * 8 + 2 * p];
#pragma unroll
            for (int j = 0; j < 8; ++j) {
                float bj = Bs[kk][lane + 32 * j];   // conflict-free: bank == lane
                unsigned long long b2;
                asm("mov.b64 %0, {%1, %1};" : "=l"(b2) : "f"(bj));
#pragma unroll
                for (int p = 0; p < 4; ++p)
                    asm("fma.rn.f32x2 %0, %1, %2, %0;"
                        : "+l"(acc[p][j]) : "l"(a2[p]), "l"(b2));
            }
        }
        __syncthreads();
    }

    // Unpack accumulators: v[i][j], i = local row, cols = lane + 32*j
    float v[8][8];
#pragma unroll
    for (int p = 0; p < 4; ++p)
#pragma unroll
        for (int j = 0; j < 8; ++j)
            asm("mov.b64 {%0, %1}, %2;"
                : "=f"(v[2 * p][j]), "=f"(v[2 * p + 1][j]) : "l"(acc[p][j]));

    float bv[8];
#pragma unroll
    for (int j = 0; j < 8; ++j) bv[j] = bias[lane + 32 * j];

    if (path == 0) {
        // bias -> LayerNorm (over the 256 cols of each row) -> gamma,beta -> ReLU
        float gv[8], bev[8];
        const float* gp = gc    + l * DD;
        const float* bp = betac + l * DD;
#pragma unroll
        for (int j = 0; j < 8; ++j) { gv[j] = gp[lane + 32 * j]; bev[j] = bp[lane + 32 * j]; }
#pragma unroll
        for (int i = 0; i < 8; ++i) {
            float s1 = 0.f, s2 = 0.f;
#pragma unroll
            for (int j = 0; j < 8; ++j) {
                float x = v[i][j] + bv[j];
                v[i][j] = x;
                s1 += x; s2 += x * x;
            }
            s1 = warp_sum(s1);
            s2 = warp_sum(s2);
            float mean = s1 * (1.0f / 256.0f);
            float var  = s2 * (1.0f / 256.0f) - mean * mean;
            float rs   = rsqrtf(var + 1e-5f);
            float* orow = O + (size_t)(m0 + warp * 8 + i) * DD;
#pragma unroll
            for (int j = 0; j < 8; ++j) {
                float y = (v[i][j] - mean) * rs * gv[j] + bev[j];
                orow[lane + 32 * j] = fmaxf(y, 0.f);
            }
        }
    } else {
        // bias -> ReLU
#pragma unroll
        for (int i = 0; i < 8; ++i) {
            float* orow = O + (size_t)(m0 + warp * 8 + i) * DD;
#pragma unroll
            for (int j = 0; j < 8; ++j)
                orow[lane + 32 * j] = fmaxf(v[i][j] + bv[j], 0.f);
        }
    }
}

// Head: warp per (l, token). cls = x2 @ cw3 + cb3 ; tmp = y2 @ rw3 + rb3 ; coord epilogue.
__global__ __launch_bounds__(256)
void head_kernel(const float* __restrict__ cw3, const float* __restrict__ cb3,
                 const float* __restrict__ rw3, const float* __restrict__ rb3,
                 const float* __restrict__ init_ref, const float* __restrict__ inter_ref,
                 float* __restrict__ out)
{
    __shared__ float Wc[10][256];   // transposed: Wc[c][k]
    __shared__ float Wr[10][256];
    const int t = threadIdx.x, lane = t & 31, warp = t >> 5;
    const int l = blockIdx.x / 3600;                // 3600 blocks per level (28800/8)

    for (int idx = t; idx < 2560; idx += 256) {
        int k = idx / 10, c = idx - k * 10;
        Wc[c][k] = cw3[l * 2560 + idx];
        Wr[c][k] = rw3[l * 2560 + idx];
    }
    __syncthreads();

    const int m = (blockIdx.x % 3600) * 8 + warp;   // token in (q*B+b) order
    const int q = m >> 5, b = m & 31;
    const float* xrow = g_x2 + ((size_t)l * MM + m) * DD;
    const float* yrow = g_y2 + ((size_t)l * MM + m) * DD;

    float xa[10], ya[10];
#pragma unroll
    for (int c = 0; c < 10; ++c) { xa[c] = 0.f; ya[c] = 0.f; }
#pragma unroll
    for (int jj = 0; jj < 8; ++jj) {
        int k = lane + 32 * jj;
        float xv = xrow[k], yv = yrow[k];
#pragma unroll
        for (int c = 0; c < 10; ++c) {
            xa[c] = fmaf(xv, Wc[c][k], xa[c]);
            ya[c] = fmaf(yv, Wr[c][k], ya[c]);
        }
    }
#pragma unroll
    for (int c = 0; c < 10; ++c) { xa[c] = warp_sum(xa[c]); ya[c] = warp_sum(ya[c]); }

    if (lane == 0) {
        const size_t base = (((size_t)l * BB + b) * QQ + q) * 10;
        float tmp[10];
#pragma unroll
        for (int c = 0; c < 10; ++c) {
            out[base + c] = xa[c] + cb3[l * 10 + c];   // cls scores
            tmp[c] = ya[c] + rb3[l * 10 + c];
        }
        const float* rp = (l == 0)
            ? (init_ref + ((size_t)b * QQ + q) * 3)
            : (inter_ref + (((size_t)(l - 1) * BB + b) * QQ + q) * 3);
        float r[3];
#pragma unroll
        for (int i = 0; i < 3; ++i) {
            float x  = fminf(fmaxf(rp[i], 0.f), 1.f);
            float x1 = fmaxf(x, 1e-5f);
            float x2 = fmaxf(1.f - x, 1e-5f);
            r[i] = logf(x1 / x2);                      // inverse sigmoid
        }
        float xy0 = 1.f / (1.f + expf(-(tmp[0] + r[0])));
        float xy1 = 1.f / (1.f + expf(-(tmp[1] + r[1])));
        float z   = 1.f / (1.f + expf(-(tmp[4] + r[2])));
        float* co = out + (size_t)L6 * BB * QQ * 10 + base;   // bbox preds
        co[0] = xy0 * 102.4f - 51.2f;
        co[1] = xy1 * 102.4f - 51.2f;
        co[2] = tmp[2];
        co[3] = tmp[3];
        co[4] = z * 8.0f - 5.0f;
        co[5] = tmp[5]; co[6] = tmp[6]; co[7] = tmp[7]; co[8] = tmp[8]; co[9] = tmp[9];
    }
}

extern "C" void kernel_launch(void* const* d_in, const int* in_sizes, int n_in,
                              void* d_out, int out_size) {
    const float* hs        = (const float*)d_in[0];
    const float* init_ref  = (const float*)d_in[1];
    const float* inter_ref = (const float*)d_in[2];
    const float* cls_w1    = (const float*)d_in[3];
    const float* cls_b1    = (const float*)d_in[4];
    const float* ln1_g     = (const float*)d_in[5];
    const float* ln1_b     = (const float*)d_in[6];
    const float* cls_w2    = (const float*)d_in[7];
    const float* cls_b2    = (const float*)d_in[8];
    const float* ln2_g     = (const float*)d_in[9];
    const float* ln2_b     = (const float*)d_in[10];
    const float* cls_w3    = (const float*)d_in[11];
    const float* cls_b3    = (const float*)d_in[12];
    const float* reg_w1    = (const float*)d_in[13];
    const float* reg_b1    = (const float*)d_in[14];
    const float* reg_w2    = (const float*)d_in[15];
    const float* reg_b2    = (const float*)d_in[16];
    const float* reg_w3    = (const float*)d_in[17];
    const float* reg_b3    = (const float*)d_in[18];
    float* out = (float*)d_out;

    dim3 grid(MM / 64, 2, L6);   // 450 x {cls,reg} x 6 levels
    fused_mlp_kernel<<<grid, 256>>>(0, hs, cls_w1, cls_b1, ln1_g, ln1_b, reg_w1, reg_b1);
    fused_mlp_kernel<<<grid, 256>>>(1, hs, cls_w2, cls_b2, ln2_g, ln2_b, reg_w2, reg_b2);
    head_kernel<<<L6 * (MM / 8), 256>>>(cls_w3, cls_b3, reg_w3, reg_b3,
                                        init_ref, inter_ref, out);
}

// round 4
// speedup vs baseline: 1.0011x; 1.0007x over previous
#include <cuda_runtime.h>
#include <math.h>

#define L6 6
#define BB 32
#define QQ 900
#define DD 256
#define MM (BB*QQ)                 // 28800 tokens per level
#define MD ((size_t)MM*(size_t)DD) // per-level elements

// Scratch (device globals: allocation-free per harness rules)
__device__ float g_x1[(size_t)L6*MM*DD];
__device__ float g_x2[(size_t)L6*MM*DD];
__device__ float g_y1[(size_t)L6*MM*DD];
__device__ float g_y2[(size_t)L6*MM*DD];

__device__ __forceinline__ float warp_sum(float v) {
#pragma unroll
    for (int off = 16; off; off >>= 1)
        v += __shfl_xor_sync(0xffffffffu, v, off);
    return v;
}

// One block computes a 64-row x 256-col output tile (full N => LN can be fused).
// blockIdx.y: 0 = cls path (Linear+LN+ReLU), 1 = reg path (Linear+ReLU)
// blockIdx.z: level
// stage 0: A = hs[l]; stage 1: A = g_x1/g_y1
__global__ __launch_bounds__(256, 2)
void fused_mlp_kernel(int stage,
                      const float* __restrict__ hs,
                      const float* __restrict__ Wc, const float* __restrict__ bc,
                      const float* __restrict__ gc, const float* __restrict__ betac,
                      const float* __restrict__ Wr, const float* __restrict__ br)
{
    const int l    = blockIdx.z;
    const int path = blockIdx.y;
    const int m0   = blockIdx.x * 64;
    const int t    = threadIdx.x;
    const int lane = t & 31, warp = t >> 5;

    const float* A;
    float* O;
    if (stage == 0) {
        A = hs + (size_t)l * MD;                       // hs[l] is [Q*B, D] contiguous, m = q*B+b
        O = (path ? g_y1 : g_x1) + (size_t)l * MD;
    } else {
        A = (path ? g_y1 : g_x1) + (size_t)l * MD;
        O = (path ? g_y2 : g_x2) + (size_t)l * MD;
    }
    const float* W    = (path ? Wr : Wc) + (size_t)l * DD * DD;   // [K,N] row-major
    const float* bias = (path ? br : bc) + l * DD;

    __shared__ float As[32][66];    // [k][m] transposed A tile (66: 8B-aligned rows, pad)
    __shared__ float Bs[32][256];   // [k][n]

    // accumulators: rows paired in f32x2 (p -> rows 2p,2p+1), 8 cols (lane + 32*j)
    unsigned long long acc[4][8];
#pragma unroll
    for (int p = 0; p < 4; ++p)
#pragma unroll
        for (int j = 0; j < 8; ++j) acc[p][j] = 0ull;

    for (int kt = 0; kt < 8; ++kt) {
        // Load A tile 64x32, transpose into As[k][m]
#pragma unroll
        for (int s = 0; s < 2; ++s) {
            int id = t + 256 * s;            // 0..511 float4s
            int r  = id >> 3;                // 0..63
            int c4 = (id & 7) << 2;          // 0..28
            const float4 f = *(const float4*)&A[(size_t)(m0 + r) * DD + kt * 32 + c4];
            As[c4 + 0][r] = f.x;
            As[c4 + 1][r] = f.y;
            As[c4 + 2][r] = f.z;
            As[c4 + 3][r] = f.w;
        }
        // Load B tile 32x256 (direct copy)
#pragma unroll
        for (int s = 0; s < 8; ++s) {
            int id = t + 256 * s;            // 0..2047 float4s
            int kr = id >> 6;                // 0..31
            int c4 = (id & 63) << 2;         // 0..252
            *(float4*)&Bs[kr][c4] = *(const float4*)&W[(size_t)(kt * 32 + kr) * DD + c4];
        }
        __syncthreads();

#pragma unroll 8
        for (int kk = 0; kk < 32; ++kk) {
            unsigned long long a2[4];
#pragma unroll
            for (int p = 0; p < 4; ++p)      // LDS.64 broadcast (all lanes same addr)
                a2[p] = *(const unsigned long long*)&As[kk][warp * 8 + 2 * p];
#pragma unroll
            for (int j = 0; j < 8; ++j) {
                float bj = Bs[kk][lane + 32 * j];   // conflict-free: bank == lane
                unsigned long long b2;
                asm("mov.b64 %0, {%1, %1};" : "=l"(b2) : "f"(bj));
#pragma unroll
                for (int p = 0; p < 4; ++p)
                    asm("fma.rn.f32x2 %0, %1, %2, %0;"
                        : "+l"(acc[p][j]) : "l"(a2[p]), "l"(b2));
            }
        }
        __syncthreads();
    }

    // Unpack accumulators: v[i][j], i = local row, cols = lane + 32*j
    float v[8][8];
#pragma unroll
    for (int p = 0; p < 4; ++p)
#pragma unroll
        for (int j = 0; j < 8; ++j)
            asm("mov.b64 {%0, %1}, %2;"
                : "=f"(v[2 * p][j]), "=f"(v[2 * p + 1][j]) : "l"(acc[p][j]));

    float bv[8];
#pragma unroll
    for (int j = 0; j < 8; ++j) bv[j] = bias[lane + 32 * j];

    if (path == 0) {
        // bias -> LayerNorm (over the 256 cols of each row) -> gamma,beta -> ReLU
        float gv[8], bev[8];
        const float* gp = gc    + l * DD;
        const float* bp = betac + l * DD;
#pragma unroll
        for (int j = 0; j < 8; ++j) { gv[j] = gp[lane + 32 * j]; bev[j] = bp[lane + 32 * j]; }
#pragma unroll
        for (int i = 0; i < 8; ++i) {
            float s1 = 0.f, s2 = 0.f;
#pragma unroll
            for (int j = 0; j < 8; ++j) {
                float x = v[i][j] + bv[j];
                v[i][j] = x;
                s1 += x; s2 += x * x;
            }
            s1 = warp_sum(s1);
            s2 = warp_sum(s2);
            float mean = s1 * (1.0f / 256.0f);
            float var  = s2 * (1.0f / 256.0f) - mean * mean;
            float rs   = rsqrtf(var + 1e-5f);
            float* orow = O + (size_t)(m0 + warp * 8 + i) * DD;
#pragma unroll
            for (int j = 0; j < 8; ++j) {
                float y = (v[i][j] - mean) * rs * gv[j] + bev[j];
                orow[lane + 32 * j] = fmaxf(y, 0.f);
            }
        }
    } else {
        // bias -> ReLU
#pragma unroll
        for (int i = 0; i < 8; ++i) {
            float* orow = O + (size_t)(m0 + warp * 8 + i) * DD;
#pragma unroll
            for (int j = 0; j < 8; ++j)
                orow[lane + 32 * j] = fmaxf(v[i][j] + bv[j], 0.f);
        }
    }
}

// Head: warp per (l, token). cls = x2 @ cw3 + cb3 ; tmp = y2 @ rw3 + rb3 ; coord epilogue.
__global__ __launch_bounds__(256)
void head_kernel(const float* __restrict__ cw3, const float* __restrict__ cb3,
                 const float* __restrict__ rw3, const float* __restrict__ rb3,
                 const float* __restrict__ init_ref, const float* __restrict__ inter_ref,
                 float* __restrict__ out)
{
    __shared__ float Wc[10][256];   // transposed: Wc[c][k]
    __shared__ float Wr[10][256];
    const int t = threadIdx.x, lane = t & 31, warp = t >> 5;
    const int l = blockIdx.x / 3600;                // 3600 blocks per level (28800/8)

    for (int idx = t; idx < 2560; idx += 256) {
        int k = idx / 10, c = idx - k * 10;
        Wc[c][k] = cw3[l * 2560 + idx];
        Wr[c][k] = rw3[l * 2560 + idx];
    }
    __syncthreads();

    const int m = (blockIdx.x % 3600) * 8 + warp;   // token in (q*B+b) order
    const int q = m >> 5, b = m & 31;
    const float* xrow = g_x2 + ((size_t)l * MM + m) * DD;
    const float* yrow = g_y2 + ((size_t)l * MM + m) * DD;

    float xa[10], ya[10];
#pragma unroll
    for (int c = 0; c < 10; ++c) { xa[c] = 0.f; ya[c] = 0.f; }
#pragma unroll
    for (int jj = 0; jj < 8; ++jj) {
        int k = lane + 32 * jj;
        float xv = xrow[k], yv = yrow[k];
#pragma unroll
        for (int c = 0; c < 10; ++c) {
            xa[c] = fmaf(xv, Wc[c][k], xa[c]);
            ya[c] = fmaf(yv, Wr[c][k], ya[c]);
        }
    }
#pragma unroll
    for (int c = 0; c < 10; ++c) { xa[c] = warp_sum(xa[c]); ya[c] = warp_sum(ya[c]); }

    if (lane == 0) {
        const size_t base = (((size_t)l * BB + b) * QQ + q) * 10;
        float tmp[10];
#pragma unroll
        for (int c = 0; c < 10; ++c) {
            out[base + c] = xa[c] + cb3[l * 10 + c];   // cls scores
            tmp[c] = ya[c] + rb3[l * 10 + c];
        }
        const float* rp = (l == 0)
            ? (init_ref + ((size_t)b * QQ + q) * 3)
            : (inter_ref + (((size_t)(l - 1) * BB + b) * QQ + q) * 3);
        float r[3];
#pragma unroll
        for (int i = 0; i < 3; ++i) {
            float x  = fminf(fmaxf(rp[i], 0.f), 1.f);
            float x1 = fmaxf(x, 1e-5f);
            float x2 = fmaxf(1.f - x, 1e-5f);
            r[i] = logf(x1 / x2);                      // inverse sigmoid
        }
        float xy0 = 1.f / (1.f + expf(-(tmp[0] + r[0])));
        float xy1 = 1.f / (1.f + expf(-(tmp[1] + r[1])));
        float z   = 1.f / (1.f + expf(-(tmp[4] + r[2])));
        float* co = out + (size_t)L6 * BB * QQ * 10 + base;   // bbox preds
        co[0] = xy0 * 102.4f - 51.2f;
        co[1] = xy1 * 102.4f - 51.2f;
        co[2] = tmp[2];
        co[3] = tmp[3];
        co[4] = z * 8.0f - 5.0f;
        co[5] = tmp[5]; co[6] = tmp[6]; co[7] = tmp[7]; co[8] = tmp[8]; co[9] = tmp[9];
    }
}

extern "C" void kernel_launch(void* const* d_in, const int* in_sizes, int n_in,
                              void* d_out, int out_size) {
    const float* hs        = (const float*)d_in[0];
    const float* init_ref  = (const float*)d_in[1];
    const float* inter_ref = (const float*)d_in[2];
    const float* cls_w1    = (const float*)d_in[3];
    const float* cls_b1    = (const float*)d_in[4];
    const float* ln1_g     = (const float*)d_in[5];
    const float* ln1_b     = (const float*)d_in[6];
    const float* cls_w2    = (const float*)d_in[7];
    const float* cls_b2    = (const float*)d_in[8];
    const float* ln2_g     = (const float*)d_in[9];
    const float* ln2_b     = (const float*)d_in[10];
    const float* cls_w3    = (const float*)d_in[11];
    const float* cls_b3    = (const float*)d_in[12];
    const float* reg_w1    = (const float*)d_in[13];
    const float* reg_b1    = (const float*)d_in[14];
    const float* reg_w2    = (const float*)d_in[15];
    const float* reg_b2    = (const float*)d_in[16];
    const float* reg_w3    = (const float*)d_in[17];
    const float* reg_b3    = (const float*)d_in[18];
    float* out = (float*)d_out;

    dim3 grid(MM / 64, 2, L6);   // 450 x {cls,reg} x 6 levels
    fused_mlp_kernel<<<grid, 256>>>(0, hs, cls_w1, cls_b1, ln1_g, ln1_b, reg_w1, reg_b1);
    fused_mlp_kernel<<<grid, 256>>>(1, hs, cls_w2, cls_b2, ln2_g, ln2_b, reg_w2, reg_b2);
    head_kernel<<<L6 * (MM / 8), 256>>>(cls_w3, cls_b3, reg_w3, reg_b3,
                                        init_ref, inter_ref, out);
}

// round 6
// speedup vs baseline: 1.7160x; 1.7141x over previous
#include <cuda_runtime.h>
#include <cuda_bf16.h>
#include <math.h>
#include <stdint.h>

#define L6 6
#define BB 32
#define QQ 900
#define DD 256
#define MM (BB*QQ)                 // 28800 tokens per level
#define MD ((size_t)MM*(size_t)DD)

// ---------------- scratch (device globals; allocation-free) ----------------
__device__ float g_x2[(size_t)L6*MM*DD];
__device__ float g_y2[(size_t)L6*MM*DD];
__device__ __nv_bfloat16 g_x1h[(size_t)L6*MM*DD];
__device__ __nv_bfloat16 g_x1l[(size_t)L6*MM*DD];
__device__ __nv_bfloat16 g_y1h[(size_t)L6*MM*DD];
__device__ __nv_bfloat16 g_y1l[(size_t)L6*MM*DD];
// transposed weights bf16 hi/lo: [widx][L][N=256][K=256]; widx: 0=cls_w1 1=reg_w1 2=cls_w2 3=reg_w2
__device__ __nv_bfloat16 g_wb_hi[(size_t)4*L6*DD*DD];
__device__ __nv_bfloat16 g_wb_lo[(size_t)4*L6*DD*DD];

// ---------------- helpers ----------------
__device__ __forceinline__ float warp_sum(float v) {
#pragma unroll
    for (int off = 16; off; off >>= 1)
        v += __shfl_xor_sync(0xffffffffu, v, off);
    return v;
}

__device__ __forceinline__ uint32_t pack_hi2(float x, float y, uint32_t& lo) {
    __nv_bfloat16 hx = __float2bfloat16(x), hy = __float2bfloat16(y);
    __nv_bfloat16 lx = __float2bfloat16(x - __bfloat162float(hx));
    __nv_bfloat16 ly = __float2bfloat16(y - __bfloat162float(hy));
    __nv_bfloat162 h(hx, hy), l2(lx, ly);
    lo = *reinterpret_cast<uint32_t*>(&l2);
    return *reinterpret_cast<uint32_t*>(&h);
}

__device__ __forceinline__ void mma16816(float* c, const uint32_t a[4],
                                         uint32_t b0, uint32_t b1) {
    asm volatile(
        "mma.sync.aligned.m16n8k16.row.col.f32.bf16.bf16.f32 "
        "{%0,%1,%2,%3}, {%4,%5,%6,%7}, {%8,%9}, {%0,%1,%2,%3};"
        : "+f"(c[0]), "+f"(c[1]), "+f"(c[2]), "+f"(c[3])
        : "r"(a[0]), "r"(a[1]), "r"(a[2]), "r"(a[3]), "r"(b0), "r"(b1));
}

// ---------------- weight transpose + bf16 hi/lo split ----------------
__global__ void transpose_weights_kernel(const float* __restrict__ w0, const float* __restrict__ w1,
                                         const float* __restrict__ w2, const float* __restrict__ w3)
{
    __shared__ float sT[32][33];
    const float* srcs[4] = {w0, w1, w2, w3};
    const int z = blockIdx.z;
    const int mat = z / L6, l = z - mat * L6;
    const int k0 = blockIdx.y * 32, n0 = blockIdx.x * 32;
    const float* W = srcs[mat] + (size_t)l * DD * DD;   // [K,N] row-major
    sT[threadIdx.y][threadIdx.x] = W[(size_t)(k0 + threadIdx.y) * DD + n0 + threadIdx.x];
    __syncthreads();
    float v = sT[threadIdx.x][threadIdx.y];             // = W[k0+tx][n0+ty]
    __nv_bfloat16 hi = __float2bfloat16(v);
    __nv_bfloat16 lo = __float2bfloat16(v - __bfloat162float(hi));
    size_t o = (((size_t)mat * L6 + l) * DD + (n0 + threadIdx.y)) * DD + k0 + threadIdx.x;
    g_wb_hi[o] = hi;
    g_wb_lo[o] = lo;
}

// ---------------- HMMA GEMM stage ----------------
// Per CTA: D[128,256] = A[128,256] @ W^T + bias, then (LN+)ReLU epilogue in-block.
// grid: x = M tile (225), y = path (0=cls with LN, 1=reg), z = level.
// STAGE 0: A = hs fp32 (converted in-flight), output -> hi/lo bf16 scratch.
// STAGE 1: A = hi/lo bf16 scratch, output -> fp32 x2/y2.
#define LDA 80
#define A_TERM 10240                // 128 rows * 80 B
#define B_TERM 20480                // 256 rows * 80 B
#define STAGE_BYTES (2*A_TERM + 2*B_TERM)   // 61440
#define TILES_OFF 5120
#define SMEM_TOTAL (TILES_OFF + 2*STAGE_BYTES)  // 128000

template<int STAGE>
__global__ __launch_bounds__(256, 1)
void gemm_stage_kernel(const float* __restrict__ hs,
                       const float* __restrict__ bc, const float* __restrict__ gc,
                       const float* __restrict__ betac, const float* __restrict__ br)
{
    extern __shared__ char smem[];
    float* biasS  = (float*)smem;          // 256
    float* gammaS = biasS + 256;
    float* betaS  = gammaS + 256;
    float* s1buf  = betaS + 256;           // 256
    float* s2buf  = s1buf + 256;           // 256
    char*  tiles  = smem + TILES_OFF;

    const int t = threadIdx.x, lane = t & 31, wid = t >> 5;
    const int wm = wid & 3, wn = wid >> 2;       // warp tile: 32 rows x 128 cols
    const int l = blockIdx.z, path = blockIdx.y, m0 = blockIdx.x * 128;

    const int widx = STAGE * 2 + path;
    const __nv_bfloat16* Bh_g = g_wb_hi + ((size_t)widx * L6 + l) * DD * DD;
    const __nv_bfloat16* Bl_g = g_wb_lo + ((size_t)widx * L6 + l) * DD * DD;
    const float* bp = (path ? br : bc) + l * DD;
    biasS[t] = bp[t];
    if (path == 0) { gammaS[t] = gc[l * DD + t]; betaS[t] = betac[l * DD + t]; }

    const float* Ag = nullptr;
    const __nv_bfloat16 *Agh = nullptr, *Agl = nullptr;
    if (STAGE == 0) {
        Ag = hs + (size_t)l * MD + (size_t)m0 * DD;
    } else {
        Agh = (path ? g_y1h : g_x1h) + (size_t)l * MD + (size_t)m0 * DD;
        Agl = (path ? g_y1l : g_x1l) + (size_t)l * MD + (size_t)m0 * DD;
    }

    float acc[2][16][4];
#pragma unroll
    for (int mf = 0; mf < 2; ++mf)
#pragma unroll
        for (int nf = 0; nf < 16; ++nf)
#pragma unroll
            for (int i = 0; i < 4; ++i) acc[mf][nf][i] = 0.f;

    // register staging for gmem->smem pipeline
    float4 a0s[4];
    uint4  a1h[2], a1l[2];
    uint4  bhs[4], bls[4];

    auto LDG = [&](int kt) {
        const int kc = kt * 32;
        if (STAGE == 0) {
#pragma unroll
            for (int s = 0; s < 4; ++s) {
                const int idx = s * 256 + t, r = idx >> 3, c = (idx & 7) << 2;
                a0s[s] = *(const float4*)(Ag + (size_t)r * DD + kc + c);
            }
        } else {
#pragma unroll
            for (int s = 0; s < 2; ++s) {
                const int idx = s * 256 + t, r = idx >> 2, c = (idx & 3) << 3;
                a1h[s] = *(const uint4*)(Agh + (size_t)r * DD + kc + c);
                a1l[s] = *(const uint4*)(Agl + (size_t)r * DD + kc + c);
            }
        }
#pragma unroll
        for (int s = 0; s < 4; ++s) {
            const int idx = s * 256 + t, n = idx >> 2, c = (idx & 3) << 3;
            bhs[s] = *(const uint4*)(Bh_g + (size_t)n * DD + kc + c);
            bls[s] = *(const uint4*)(Bl_g + (size_t)n * DD + kc + c);
        }
    };
    auto STS = [&](int buf) {
        char* Ah = tiles + buf * STAGE_BYTES;
        char* Al = Ah + A_TERM;
        char* Bh = Ah + 2 * A_TERM;
        char* Bl = Bh + B_TERM;
        if (STAGE == 0) {
#pragma unroll
            for (int s = 0; s < 4; ++s) {
                const int idx = s * 256 + t, r = idx >> 3, c = (idx & 7) << 2;
                uint32_t lo0, lo1;
                const uint32_t hi0 = pack_hi2(a0s[s].x, a0s[s].y, lo0);
                const uint32_t hi1 = pack_hi2(a0s[s].z, a0s[s].w, lo1);
                *(uint2*)(Ah + r * LDA + c * 2) = make_uint2(hi0, hi1);
                *(uint2*)(Al + r * LDA + c * 2) = make_uint2(lo0, lo1);
            }
        } else {
#pragma unroll
            for (int s = 0; s < 2; ++s) {
                const int idx = s * 256 + t, r = idx >> 2, c = (idx & 3) << 3;
                *(uint4*)(Ah + r * LDA + c * 2) = a1h[s];
                *(uint4*)(Al + r * LDA + c * 2) = a1l[s];
            }
        }
#pragma unroll
        for (int s = 0; s < 4; ++s) {
            const int idx = s * 256 + t, n = idx >> 2, c = (idx & 3) << 3;
            *(uint4*)(Bh + n * LDA + c * 2) = bhs[s];
            *(uint4*)(Bl + n * LDA + c * 2) = bls[s];
        }
    };

    LDG(0);
    __syncthreads();   // biasS etc. written
    STS(0);
    __syncthreads();

    const int gr = lane >> 2, gc2 = (lane & 3) << 1;

#pragma unroll 1
    for (int kt = 0; kt < 8; ++kt) {
        if (kt < 7) LDG(kt + 1);
        {
            const char* Ah = tiles + (kt & 1) * STAGE_BYTES;
            const char* Al = Ah + A_TERM;
            const char* Bh = Ah + 2 * A_TERM;
            const char* Bl = Bh + B_TERM;
#pragma unroll
            for (int ks = 0; ks < 2; ++ks) {
                const int kb = ks * 32 + gc2 * 2;
                uint32_t ah[2][4], al[2][4];
#pragma unroll
                for (int mf = 0; mf < 2; ++mf) {
                    const int ro = (wm * 32 + mf * 16 + gr) * LDA + kb;
                    ah[mf][0] = *(const uint32_t*)(Ah + ro);
                    ah[mf][1] = *(const uint32_t*)(Ah + ro + 8 * LDA);
                    ah[mf][2] = *(const uint32_t*)(Ah + ro + 16);
                    ah[mf][3] = *(const uint32_t*)(Ah + ro + 8 * LDA + 16);
                    al[mf][0] = *(const uint32_t*)(Al + ro);
                    al[mf][1] = *(const uint32_t*)(Al + ro + 8 * LDA);
                    al[mf][2] = *(const uint32_t*)(Al + ro + 16);
                    al[mf][3] = *(const uint32_t*)(Al + ro + 8 * LDA + 16);
                }
#pragma unroll
                for (int nf = 0; nf < 16; ++nf) {
                    const int no = (wn * 128 + nf * 8 + gr) * LDA + kb;
                    const uint32_t bh0 = *(const uint32_t*)(Bh + no);
                    const uint32_t bh1 = *(const uint32_t*)(Bh + no + 16);
                    const uint32_t bl0 = *(const uint32_t*)(Bl + no);
                    const uint32_t bl1 = *(const uint32_t*)(Bl + no + 16);
#pragma unroll
                    for (int mf = 0; mf < 2; ++mf) {
                        mma16816(acc[mf][nf], ah[mf], bh0, bh1);   // hi*hi
                        mma16816(acc[mf][nf], al[mf], bh0, bh1);   // lo*hi
                        mma16816(acc[mf][nf], ah[mf], bl0, bl1);   // hi*lo
                    }
                }
            }
        }
        if (kt < 7) STS((kt + 1) & 1);
        __syncthreads();
    }

    // ---------------- epilogue ----------------
    // add bias
#pragma unroll
    for (int nf = 0; nf < 16; ++nf) {
        const int cb = wn * 128 + nf * 8 + gc2;
        const float b0 = biasS[cb], b1 = biasS[cb + 1];
#pragma unroll
        for (int mf = 0; mf < 2; ++mf) {
            acc[mf][nf][0] += b0; acc[mf][nf][1] += b1;
            acc[mf][nf][2] += b0; acc[mf][nf][3] += b1;
        }
    }

    float mean_[2][2], rs_[2][2];
    if (path == 0) {
        float s1[2][2] = {{0.f,0.f},{0.f,0.f}}, s2[2][2] = {{0.f,0.f},{0.f,0.f}};
#pragma unroll
        for (int nf = 0; nf < 16; ++nf)
#pragma unroll
            for (int mf = 0; mf < 2; ++mf) {
                s1[mf][0] += acc[mf][nf][0] + acc[mf][nf][1];
                s2[mf][0] += acc[mf][nf][0]*acc[mf][nf][0] + acc[mf][nf][1]*acc[mf][nf][1];
                s1[mf][1] += acc[mf][nf][2] + acc[mf][nf][3];
                s2[mf][1] += acc[mf][nf][2]*acc[mf][nf][2] + acc[mf][nf][3]*acc[mf][nf][3];
            }
#pragma unroll
        for (int mf = 0; mf < 2; ++mf)
#pragma unroll
            for (int h = 0; h < 2; ++h) {
                s1[mf][h] += __shfl_xor_sync(0xffffffffu, s1[mf][h], 1);
                s1[mf][h] += __shfl_xor_sync(0xffffffffu, s1[mf][h], 2);
                s2[mf][h] += __shfl_xor_sync(0xffffffffu, s2[mf][h], 1);
                s2[mf][h] += __shfl_xor_sync(0xffffffffu, s2[mf][h], 2);
            }
        if ((lane & 3) == 0) {
#pragma unroll
            for (int mf = 0; mf < 2; ++mf)
#pragma unroll
                for (int h = 0; h < 2; ++h) {
                    const int row = wm * 32 + mf * 16 + h * 8 + gr;
                    s1buf[wn * 128 + row] = s1[mf][h];
                    s2buf[wn * 128 + row] = s2[mf][h];
                }
        }
        __syncthreads();
#pragma unroll
        for (int mf = 0; mf < 2; ++mf)
#pragma unroll
            for (int h = 0; h < 2; ++h) {
                const int row = wm * 32 + mf * 16 + h * 8 + gr;
                const float t1 = s1buf[row] + s1buf[128 + row];
                const float t2 = s2buf[row] + s2buf[128 + row];
                const float mean = t1 * (1.0f / 256.0f);
                const float var  = t2 * (1.0f / 256.0f) - mean * mean;
                mean_[mf][h] = mean;
                rs_[mf][h]   = rsqrtf(var + 1e-5f);
            }
    }

    uint32_t* Ohi = nullptr; uint32_t* Olo = nullptr; float* Of = nullptr;
    if (STAGE == 0) {
        Ohi = (uint32_t*)((path ? g_y1h : g_x1h) + (size_t)l * MD + (size_t)m0 * DD);
        Olo = (uint32_t*)((path ? g_y1l : g_x1l) + (size_t)l * MD + (size_t)m0 * DD);
    } else {
        Of = (path ? g_y2 : g_x2) + (size_t)l * MD + (size_t)m0 * DD;
    }

#pragma unroll
    for (int nf = 0; nf < 16; ++nf) {
        const int cb = wn * 128 + nf * 8 + gc2;
        float g0 = 1.f, g1 = 1.f, be0 = 0.f, be1 = 0.f;
        if (path == 0) { g0 = gammaS[cb]; g1 = gammaS[cb + 1]; be0 = betaS[cb]; be1 = betaS[cb + 1]; }
#pragma unroll
        for (int mf = 0; mf < 2; ++mf) {
            float y[4];
            if (path == 0) {
                y[0] = (acc[mf][nf][0] - mean_[mf][0]) * rs_[mf][0] * g0 + be0;
                y[1] = (acc[mf][nf][1] - mean_[mf][0]) * rs_[mf][0] * g1 + be1;
                y[2] = (acc[mf][nf][2] - mean_[mf][1]) * rs_[mf][1] * g0 + be0;
                y[3] = (acc[mf][nf][3] - mean_[mf][1]) * rs_[mf][1] * g1 + be1;
            } else {
                y[0] = acc[mf][nf][0]; y[1] = acc[mf][nf][1];
                y[2] = acc[mf][nf][2]; y[3] = acc[mf][nf][3];
            }
#pragma unroll
            for (int i = 0; i < 4; ++i) y[i] = fmaxf(y[i], 0.f);

            const int row0 = wm * 32 + mf * 16 + gr;
            if (STAGE == 0) {
                uint32_t lo0, lo1;
                const uint32_t hi0 = pack_hi2(y[0], y[1], lo0);
                const uint32_t hi1 = pack_hi2(y[2], y[3], lo1);
                const size_t o0 = ((size_t)row0 * DD + cb) >> 1;
                const size_t o1 = ((size_t)(row0 + 8) * DD + cb) >> 1;
                Ohi[o0] = hi0; Olo[o0] = lo0;
                Ohi[o1] = hi1; Olo[o1] = lo1;
            } else {
                *(float2*)&Of[(size_t)row0 * DD + cb]       = make_float2(y[0], y[1]);
                *(float2*)&Of[(size_t)(row0 + 8) * DD + cb] = make_float2(y[2], y[3]);
            }
        }
    }
}

// ---------------- head ----------------
__global__ __launch_bounds__(256)
void head_kernel(const float* __restrict__ cw3, const float* __restrict__ cb3,
                 const float* __restrict__ rw3, const float* __restrict__ rb3,
                 const float* __restrict__ init_ref, const float* __restrict__ inter_ref,
                 float* __restrict__ out)
{
    __shared__ float Wc[10][256];
    __shared__ float Wr[10][256];
    const int t = threadIdx.x, lane = t & 31, warp = t >> 5;
    const int l = blockIdx.x / 1800;
    const int blk = blockIdx.x % 1800;

    for (int idx = t; idx < 2560; idx += 256) {
        const int k = idx / 10, c = idx - k * 10;
        Wc[c][k] = cw3[l * 2560 + idx];
        Wr[c][k] = rw3[l * 2560 + idx];
    }
    __syncthreads();

    const int mbase = blk * 16 + warp * 2;      // 2 tokens per warp
    const float* x0 = g_x2 + ((size_t)l * MM + mbase) * DD;
    const float* y0 = g_y2 + ((size_t)l * MM + mbase) * DD;

    float xv[2][8], yv[2][8];
#pragma unroll
    for (int tok = 0; tok < 2; ++tok)
#pragma unroll
        for (int jj = 0; jj < 8; ++jj) {
            xv[tok][jj] = x0[tok * DD + lane + 32 * jj];
            yv[tok][jj] = y0[tok * DD + lane + 32 * jj];
        }

    float xa[2][10], ya[2][10];
#pragma unroll
    for (int tok = 0; tok < 2; ++tok)
#pragma unroll
        for (int c = 0; c < 10; ++c) { xa[tok][c] = 0.f; ya[tok][c] = 0.f; }

#pragma unroll
    for (int jj = 0; jj < 8; ++jj) {
        const int k = lane + 32 * jj;
#pragma unroll
        for (int c = 0; c < 10; ++c) {
            const float wc = Wc[c][k], wr = Wr[c][k];
            xa[0][c] = fmaf(xv[0][jj], wc, xa[0][c]);
            xa[1][c] = fmaf(xv[1][jj], wc, xa[1][c]);
            ya[0][c] = fmaf(yv[0][jj], wr, ya[0][c]);
            ya[1][c] = fmaf(yv[1][jj], wr, ya[1][c]);
        }
    }
#pragma unroll
    for (int tok = 0; tok < 2; ++tok)
#pragma unroll
        for (int c = 0; c < 10; ++c) {
            xa[tok][c] = warp_sum(xa[tok][c]);
            ya[tok][c] = warp_sum(ya[tok][c]);
        }

    if (lane < 2) {
        const int tok = lane;
        const int m = mbase + tok;
        const int q = m >> 5, b = m & 31;
        const size_t base = (((size_t)l * BB + b) * QQ + q) * 10;
        float tmp[10];
#pragma unroll
        for (int c = 0; c < 10; ++c) {
            out[base + c] = xa[tok][c] + cb3[l * 10 + c];
            tmp[c] = ya[tok][c] + rb3[l * 10 + c];
        }
        const float* rp = (l == 0)
            ? (init_ref + ((size_t)b * QQ + q) * 3)
            : (inter_ref + (((size_t)(l - 1) * BB + b) * QQ + q) * 3);
        float r[3];
#pragma unroll
        for (int i = 0; i < 3; ++i) {
            const float x  = fminf(fmaxf(rp[i], 0.f), 1.f);
            const float x1 = fmaxf(x, 1e-5f);
            const float x2 = fmaxf(1.f - x, 1e-5f);
            r[i] = logf(x1 / x2);
        }
        const float xy0 = 1.f / (1.f + expf(-(tmp[0] + r[0])));
        const float xy1 = 1.f / (1.f + expf(-(tmp[1] + r[1])));
        const float z   = 1.f / (1.f + expf(-(tmp[4] + r[2])));
        float* co = out + (size_t)L6 * BB * QQ * 10 + base;
        co[0] = xy0 * 102.4f - 51.2f;
        co[1] = xy1 * 102.4f - 51.2f;
        co[2] = tmp[2];
        co[3] = tmp[3];
        co[4] = z * 8.0f - 5.0f;
        co[5] = tmp[5]; co[6] = tmp[6]; co[7] = tmp[7]; co[8] = tmp[8]; co[9] = tmp[9];
    }
}

extern "C" void kernel_launch(void* const* d_in, const int* in_sizes, int n_in,
                              void* d_out, int out_size) {
    const float* hs        = (const float*)d_in[0];
    const float* init_ref  = (const float*)d_in[1];
    const float* inter_ref = (const float*)d_in[2];
    const float* cls_w1    = (const float*)d_in[3];
    const float* cls_b1    = (const float*)d_in[4];
    const float* ln1_g     = (const float*)d_in[5];
    const float* ln1_b     = (const float*)d_in[6];
    const float* cls_w2    = (const float*)d_in[7];
    const float* cls_b2    = (const float*)d_in[8];
    const float* ln2_g     = (const float*)d_in[9];
    const float* ln2_b     = (const float*)d_in[10];
    const float* cls_w3    = (const float*)d_in[11];
    const float* cls_b3    = (const float*)d_in[12];
    const float* reg_w1    = (const float*)d_in[13];
    const float* reg_b1    = (const float*)d_in[14];
    const float* reg_w2    = (const float*)d_in[15];
    const float* reg_b2    = (const float*)d_in[16];
    const float* reg_w3    = (const float*)d_in[17];
    const float* reg_b3    = (const float*)d_in[18];
    float* out = (float*)d_out;

    cudaFuncSetAttribute(gemm_stage_kernel<0>, cudaFuncAttributeMaxDynamicSharedMemorySize, SMEM_TOTAL);
    cudaFuncSetAttribute(gemm_stage_kernel<1>, cudaFuncAttributeMaxDynamicSharedMemorySize, SMEM_TOTAL);

    transpose_weights_kernel<<<dim3(8, 8, 4 * L6), dim3(32, 32)>>>(cls_w1, reg_w1, cls_w2, reg_w2);

    dim3 grid(MM / 128, 2, L6);   // 225 x {cls,reg} x 6
    gemm_stage_kernel<0><<<grid, 256, SMEM_TOTAL>>>(hs, cls_b1, ln1_g, ln1_b, reg_b1);
    gemm_stage_kernel<1><<<grid, 256, SMEM_TOTAL>>>(hs, cls_b2, ln2_g, ln2_b, reg_b2);

    head_kernel<<<L6 * (MM / 16), 256>>>(cls_w3, cls_b3, reg_w3, reg_b3,
                                         init_ref, inter_ref, out);
}

// round 7
// speedup vs baseline: 1.9047x; 1.1099x over previous
#include <cuda_runtime.h>
#include <cuda_bf16.h>
#include <math.h>
#include <stdint.h>

#define L6 6
#define BB 32
#define QQ 900
#define DD 256
#define MM (BB*QQ)                 // 28800 tokens per level
#define MD ((size_t)MM*(size_t)DD)

// ---------------- scratch (device globals; allocation-free) ----------------
__device__ __nv_bfloat16 g_ah[(size_t)L6*MM*DD];   // hs split hi
__device__ __nv_bfloat16 g_al[(size_t)L6*MM*DD];   // hs split lo
__device__ __nv_bfloat16 g_x1h[(size_t)L6*MM*DD];
__device__ __nv_bfloat16 g_x1l[(size_t)L6*MM*DD];
__device__ __nv_bfloat16 g_y1h[(size_t)L6*MM*DD];
__device__ __nv_bfloat16 g_y1l[(size_t)L6*MM*DD];
// transposed weights bf16 hi/lo: [widx][L][N=256][K=256]; widx: 0=cls_w1 1=reg_w1 2=cls_w2 3=reg_w2
__device__ __nv_bfloat16 g_wb_hi[(size_t)4*L6*DD*DD];
__device__ __nv_bfloat16 g_wb_lo[(size_t)4*L6*DD*DD];

// ---------------- helpers ----------------
__device__ __forceinline__ uint32_t smem_u32(const void* p) {
    uint32_t a;
    asm("{ .reg .u64 t; cvta.to.shared.u64 t, %1; cvt.u32.u64 %0, t; }" : "=r"(a) : "l"(p));
    return a;
}
#define CP_ASYNC16(dst, src) \
    asm volatile("cp.async.cg.shared.global [%0], [%1], 16;" :: "r"(dst), "l"(src))
#define CP_COMMIT() asm volatile("cp.async.commit_group;" ::: "memory")
#define CP_WAIT(n)  asm volatile("cp.async.wait_group %0;" :: "n"(n) : "memory")

__device__ __forceinline__ uint32_t pack_hi2(float x, float y, uint32_t& lo) {
    __nv_bfloat16 hx = __float2bfloat16(x), hy = __float2bfloat16(y);
    __nv_bfloat16 lx = __float2bfloat16(x - __bfloat162float(hx));
    __nv_bfloat16 ly = __float2bfloat16(y - __bfloat162float(hy));
    __nv_bfloat162 h(hx, hy), l2(lx, ly);
    lo = *reinterpret_cast<uint32_t*>(&l2);
    return *reinterpret_cast<uint32_t*>(&h);
}

__device__ __forceinline__ void mma16816(float* c, const uint32_t a[4],
                                         uint32_t b0, uint32_t b1) {
    asm volatile(
        "mma.sync.aligned.m16n8k16.row.col.f32.bf16.bf16.f32 "
        "{%0,%1,%2,%3}, {%4,%5,%6,%7}, {%8,%9}, {%0,%1,%2,%3};"
        : "+f"(c[0]), "+f"(c[1]), "+f"(c[2]), "+f"(c[3])
        : "r"(a[0]), "r"(a[1]), "r"(a[2]), "r"(a[3]), "r"(b0), "r"(b1));
}

// ---------------- pre-pass: hs fp32 -> hi/lo bf16 ----------------
__global__ __launch_bounds__(512)
void split_hs_kernel(const float* __restrict__ hs) {
    const size_t idx = (size_t)blockIdx.x * blockDim.x + threadIdx.x;  // float4 index
    const float4 f = ((const float4*)hs)[idx];
    uint32_t lo0, lo1;
    const uint32_t hi0 = pack_hi2(f.x, f.y, lo0);
    const uint32_t hi1 = pack_hi2(f.z, f.w, lo1);
    ((uint2*)g_ah)[idx] = make_uint2(hi0, hi1);
    ((uint2*)g_al)[idx] = make_uint2(lo0, lo1);
}

// ---------------- weight transpose + bf16 hi/lo split ----------------
__global__ void transpose_weights_kernel(const float* __restrict__ w0, const float* __restrict__ w1,
                                         const float* __restrict__ w2, const float* __restrict__ w3)
{
    __shared__ float sT[32][33];
    const float* srcs[4] = {w0, w1, w2, w3};
    const int z = blockIdx.z;
    const int mat = z / L6, l = z - mat * L6;
    const int k0 = blockIdx.y * 32, n0 = blockIdx.x * 32;
    const float* W = srcs[mat] + (size_t)l * DD * DD;   // [K,N] row-major
    sT[threadIdx.y][threadIdx.x] = W[(size_t)(k0 + threadIdx.y) * DD + n0 + threadIdx.x];
    __syncthreads();
    float v = sT[threadIdx.x][threadIdx.y];             // = W[k0+tx][n0+ty]
    __nv_bfloat16 hi = __float2bfloat16(v);
    __nv_bfloat16 lo = __float2bfloat16(v - __bfloat162float(hi));
    size_t o = (((size_t)mat * L6 + l) * DD + (n0 + threadIdx.y)) * DD + k0 + threadIdx.x;
    g_wb_hi[o] = hi;
    g_wb_lo[o] = lo;
}

// ---------------- HMMA GEMM stage (512 threads, cp.async, fused head) ----------------
// Per CTA: D[128,256] = A[128,256] @ W^T + bias, (LN+)ReLU epilogue.
// STAGE 0: A = g_ah/g_al, out -> g_x1h/l or g_y1h/l.
// STAGE 1: A = g_x1h/l (path0) or g_y1h/l (path1); epilogue computes the 256->10 head
//          GEMV + (path1) coord transform and writes the FINAL output. No x2/y2 gmem.
#define LDA 80
#define A_COMP 10240                // 128 rows * 80 B
#define B_COMP 20480                // 256 rows * 80 B
#define STAGE_BYTES (2*A_COMP + 2*B_COMP)   // 61440

#define OFF_BIAS   0
#define OFF_GAMMA  1024
#define OFF_BETA   2048
#define OFF_S1     3072      // 4*128*4 = 2048
#define OFF_S2     5120
#define OFF_W3     7168      // 256*12*4 = 12288
#define OFF_PSUM   19456     // 4*128*12*4 = 24576
#define OFF_TILES  44032
#define SMEM_TOTAL (OFF_TILES + 2*STAGE_BYTES)   // 166912

template<int STAGE>
__global__ __launch_bounds__(512, 1)
void gemm_stage_kernel(const float* __restrict__ bc, const float* __restrict__ gc,
                       const float* __restrict__ betac, const float* __restrict__ br,
                       const float* __restrict__ cw3, const float* __restrict__ cb3,
                       const float* __restrict__ rw3, const float* __restrict__ rb3,
                       const float* __restrict__ init_ref, const float* __restrict__ inter_ref,
                       float* __restrict__ out)
{
    extern __shared__ char smem[];
    float* biasS  = (float*)(smem + OFF_BIAS);
    float* gammaS = (float*)(smem + OFF_GAMMA);
    float* betaS  = (float*)(smem + OFF_BETA);
    float* s1buf  = (float*)(smem + OFF_S1);
    float* s2buf  = (float*)(smem + OFF_S2);
    float* W3s    = (float*)(smem + OFF_W3);     // [256][12]
    float* psum   = (float*)(smem + OFF_PSUM);   // [4][128][12]
    char*  tiles  = smem + OFF_TILES;
    const uint32_t tiles_s = smem_u32(tiles);

    const int t = threadIdx.x, lane = t & 31, wid = t >> 5;
    const int wm = wid & 3, wn = wid >> 2;       // warp tile: 32 rows x 64 cols
    const int l = blockIdx.z, path = blockIdx.y, m0 = blockIdx.x * 128;

    const int widx = STAGE * 2 + path;
    const __nv_bfloat16* Bh_g = g_wb_hi + ((size_t)widx * L6 + l) * DD * DD;
    const __nv_bfloat16* Bl_g = g_wb_lo + ((size_t)widx * L6 + l) * DD * DD;
    const __nv_bfloat16* Agh, * Agl;
    if (STAGE == 0) {
        Agh = g_ah + (size_t)l * MD + (size_t)m0 * DD;
        Agl = g_al + (size_t)l * MD + (size_t)m0 * DD;
    } else {
        Agh = (path ? g_y1h : g_x1h) + (size_t)l * MD + (size_t)m0 * DD;
        Agl = (path ? g_y1l : g_x1l) + (size_t)l * MD + (size_t)m0 * DD;
    }

    // ---- parameter loads ----
    if (t < 256) {
        biasS[t] = ((path ? br : bc) + l * DD)[t];
        if (path == 0) { gammaS[t] = gc[l * DD + t]; betaS[t] = betac[l * DD + t]; }
    }
    if (STAGE == 1) {
        const float* w3g = (path ? rw3 : cw3) + l * 2560;
        for (int idx = t; idx < 2560; idx += 512) {
            const int k = idx / 10, nc = idx - k * 10;
            W3s[k * 12 + nc] = w3g[idx];
        }
    }

    // ---- cp.async chunk loader ----
    auto load_chunk = [&](int kt, int buf) {
        const int kc = kt * 32;
        const uint32_t base = tiles_s + buf * STAGE_BYTES;
        // A: hi + lo, 128 rows x 4 x 16B each
        {
            const int row = t >> 2, c = t & 3;
            const uint32_t d = base + row * LDA + c * 16;
            CP_ASYNC16(d,           Agh + (size_t)row * DD + kc + c * 8);
            CP_ASYNC16(d + A_COMP,  Agl + (size_t)row * DD + kc + c * 8);
        }
        // B: hi + lo, 256 rows x 4 x 16B each
#pragma unroll
        for (int s = 0; s < 2; ++s) {
            const int idx = s * 512 + t, row = idx >> 2, c = idx & 3;
            const uint32_t d = base + 2 * A_COMP + row * LDA + c * 16;
            CP_ASYNC16(d,           Bh_g + (size_t)row * DD + kc + c * 8);
            CP_ASYNC16(d + B_COMP,  Bl_g + (size_t)row * DD + kc + c * 8);
        }
    };

    float acc[2][8][4];
#pragma unroll
    for (int mf = 0; mf < 2; ++mf)
#pragma unroll
        for (int nf = 0; nf < 8; ++nf)
#pragma unroll
            for (int i = 0; i < 4; ++i) acc[mf][nf][i] = 0.f;

    load_chunk(0, 0);
    CP_COMMIT();
    __syncthreads();   // params visible

    const int gr = lane >> 2, gc2 = (lane & 3) << 1;

#pragma unroll 1
    for (int kt = 0; kt < 8; ++kt) {
        if (kt < 7) { load_chunk(kt + 1, (kt + 1) & 1); CP_COMMIT(); CP_WAIT(1); }
        else        { CP_WAIT(0); }
        __syncthreads();
        {
            const char* Ah = tiles + (kt & 1) * STAGE_BYTES;
            const char* Al = Ah + A_COMP;
            const char* Bh = Ah + 2 * A_COMP;
            const char* Bl = Bh + B_COMP;
#pragma unroll
            for (int ks = 0; ks < 2; ++ks) {
                const int kb = ks * 32 + gc2 * 2;
                uint32_t ah[2][4], al[2][4];
#pragma unroll
                for (int mf = 0; mf < 2; ++mf) {
                    const int ro = (wm * 32 + mf * 16 + gr) * LDA + kb;
                    ah[mf][0] = *(const uint32_t*)(Ah + ro);
                    ah[mf][1] = *(const uint32_t*)(Ah + ro + 8 * LDA);
                    ah[mf][2] = *(const uint32_t*)(Ah + ro + 16);
                    ah[mf][3] = *(const uint32_t*)(Ah + ro + 8 * LDA + 16);
                    al[mf][0] = *(const uint32_t*)(Al + ro);
                    al[mf][1] = *(const uint32_t*)(Al + ro + 8 * LDA);
                    al[mf][2] = *(const uint32_t*)(Al + ro + 16);
                    al[mf][3] = *(const uint32_t*)(Al + ro + 8 * LDA + 16);
                }
#pragma unroll
                for (int nf = 0; nf < 8; ++nf) {
                    const int no = (wn * 64 + nf * 8 + gr) * LDA + kb;
                    const uint32_t bh0 = *(const uint32_t*)(Bh + no);
                    const uint32_t bh1 = *(const uint32_t*)(Bh + no + 16);
                    const uint32_t bl0 = *(const uint32_t*)(Bl + no);
                    const uint32_t bl1 = *(const uint32_t*)(Bl + no + 16);
#pragma unroll
                    for (int mf = 0; mf < 2; ++mf) {
                        mma16816(acc[mf][nf], ah[mf], bh0, bh1);   // hi*hi
                        mma16816(acc[mf][nf], al[mf], bh0, bh1);   // lo*hi
                        mma16816(acc[mf][nf], ah[mf], bl0, bl1);   // hi*lo
                    }
                }
            }
        }
        __syncthreads();
    }

    // ---------------- epilogue ----------------
    // add bias
#pragma unroll
    for (int nf = 0; nf < 8; ++nf) {
        const int cb = wn * 64 + nf * 8 + gc2;
        const float b0 = biasS[cb], b1 = biasS[cb + 1];
#pragma unroll
        for (int mf = 0; mf < 2; ++mf) {
            acc[mf][nf][0] += b0; acc[mf][nf][1] += b1;
            acc[mf][nf][2] += b0; acc[mf][nf][3] += b1;
        }
    }

    float mean_[2][2], rs_[2][2];
    if (path == 0) {
        // LayerNorm stats over 256 cols: quad reduce, per-wn partials, cross-wn sum
        float s1[2][2] = {{0.f,0.f},{0.f,0.f}}, s2[2][2] = {{0.f,0.f},{0.f,0.f}};
#pragma unroll
        for (int nf = 0; nf < 8; ++nf)
#pragma unroll
            for (int mf = 0; mf < 2; ++mf) {
                s1[mf][0] += acc[mf][nf][0] + acc[mf][nf][1];
                s2[mf][0] += acc[mf][nf][0]*acc[mf][nf][0] + acc[mf][nf][1]*acc[mf][nf][1];
                s1[mf][1] += acc[mf][nf][2] + acc[mf][nf][3];
                s2[mf][1] += acc[mf][nf][2]*acc[mf][nf][2] + acc[mf][nf][3]*acc[mf][nf][3];
            }
#pragma unroll
        for (int mf = 0; mf < 2; ++mf)
#pragma unroll
            for (int h = 0; h < 2; ++h) {
                s1[mf][h] += __shfl_xor_sync(0xffffffffu, s1[mf][h], 1);
                s1[mf][h] += __shfl_xor_sync(0xffffffffu, s1[mf][h], 2);
                s2[mf][h] += __shfl_xor_sync(0xffffffffu, s2[mf][h], 1);
                s2[mf][h] += __shfl_xor_sync(0xffffffffu, s2[mf][h], 2);
            }
        if ((lane & 3) == 0) {
#pragma unroll
            for (int mf = 0; mf < 2; ++mf)
#pragma unroll
                for (int h = 0; h < 2; ++h) {
                    const int row = wm * 32 + mf * 16 + h * 8 + gr;
                    s1buf[wn * 128 + row] = s1[mf][h];
                    s2buf[wn * 128 + row] = s2[mf][h];
                }
        }
        __syncthreads();
#pragma unroll
        for (int mf = 0; mf < 2; ++mf)
#pragma unroll
            for (int h = 0; h < 2; ++h) {
                const int row = wm * 32 + mf * 16 + h * 8 + gr;
                const float t1 = s1buf[row] + s1buf[128 + row] + s1buf[256 + row] + s1buf[384 + row];
                const float t2 = s2buf[row] + s2buf[128 + row] + s2buf[256 + row] + s2buf[384 + row];
                const float mean = t1 * (1.0f / 256.0f);
                const float var  = t2 * (1.0f / 256.0f) - mean * mean;
                mean_[mf][h] = mean;
                rs_[mf][h]   = rsqrtf(var + 1e-5f);
            }
    }

    if (STAGE == 0) {
        uint32_t* Ohi = (uint32_t*)((path ? g_y1h : g_x1h) + (size_t)l * MD + (size_t)m0 * DD);
        uint32_t* Olo = (uint32_t*)((path ? g_y1l : g_x1l) + (size_t)l * MD + (size_t)m0 * DD);
#pragma unroll
        for (int nf = 0; nf < 8; ++nf) {
            const int cb = wn * 64 + nf * 8 + gc2;
            float g0 = 1.f, g1 = 1.f, be0 = 0.f, be1 = 0.f;
            if (path == 0) { g0 = gammaS[cb]; g1 = gammaS[cb + 1]; be0 = betaS[cb]; be1 = betaS[cb + 1]; }
#pragma unroll
            for (int mf = 0; mf < 2; ++mf) {
                float y[4];
                if (path == 0) {
                    y[0] = (acc[mf][nf][0] - mean_[mf][0]) * rs_[mf][0] * g0 + be0;
                    y[1] = (acc[mf][nf][1] - mean_[mf][0]) * rs_[mf][0] * g1 + be1;
                    y[2] = (acc[mf][nf][2] - mean_[mf][1]) * rs_[mf][1] * g0 + be0;
                    y[3] = (acc[mf][nf][3] - mean_[mf][1]) * rs_[mf][1] * g1 + be1;
                } else {
                    y[0] = acc[mf][nf][0]; y[1] = acc[mf][nf][1];
                    y[2] = acc[mf][nf][2]; y[3] = acc[mf][nf][3];
                }
#pragma unroll
                for (int i = 0; i < 4; ++i) y[i] = fmaxf(y[i], 0.f);
                const int row0 = wm * 32 + mf * 16 + gr;
                uint32_t lo0, lo1;
                const uint32_t hi0 = pack_hi2(y[0], y[1], lo0);
                const uint32_t hi1 = pack_hi2(y[2], y[3], lo1);
                const size_t o0 = ((size_t)row0 * DD + cb) >> 1;
                const size_t o1 = ((size_t)(row0 + 8) * DD + cb) >> 1;
                Ohi[o0] = hi0; Olo[o0] = lo0;
                Ohi[o1] = hi1; Olo[o1] = lo1;
            }
        }
    } else {
        // ---- fused head: part[slot][nc] = sum over this thread's cols of y * W3[col][nc] ----
        float part[4][10];
#pragma unroll
        for (int s = 0; s < 4; ++s)
#pragma unroll
            for (int nc = 0; nc < 10; ++nc) part[s][nc] = 0.f;

#pragma unroll
        for (int nf = 0; nf < 8; ++nf) {
            const int cb = wn * 64 + nf * 8 + gc2;
            float g0 = 1.f, g1 = 1.f, be0 = 0.f, be1 = 0.f;
            if (path == 0) { g0 = gammaS[cb]; g1 = gammaS[cb + 1]; be0 = betaS[cb]; be1 = betaS[cb + 1]; }
            float y[2][4];
#pragma unroll
            for (int mf = 0; mf < 2; ++mf) {
                if (path == 0) {
                    y[mf][0] = (acc[mf][nf][0] - mean_[mf][0]) * rs_[mf][0] * g0 + be0;
                    y[mf][1] = (acc[mf][nf][1] - mean_[mf][0]) * rs_[mf][0] * g1 + be1;
                    y[mf][2] = (acc[mf][nf][2] - mean_[mf][1]) * rs_[mf][1] * g0 + be0;
                    y[mf][3] = (acc[mf][nf][3] - mean_[mf][1]) * rs_[mf][1] * g1 + be1;
                } else {
                    y[mf][0] = acc[mf][nf][0]; y[mf][1] = acc[mf][nf][1];
                    y[mf][2] = acc[mf][nf][2]; y[mf][3] = acc[mf][nf][3];
                }
#pragma unroll
                for (int i = 0; i < 4; ++i) y[mf][i] = fmaxf(y[mf][i], 0.f);
            }
            const float* w0 = &W3s[cb * 12];
            const float* w1 = &W3s[(cb + 1) * 12];
#pragma unroll
            for (int nc = 0; nc < 10; ++nc) {
                const float a0 = w0[nc], a1 = w1[nc];
#pragma unroll
                for (int mf = 0; mf < 2; ++mf) {
                    part[mf * 2 + 0][nc] = fmaf(y[mf][0], a0, fmaf(y[mf][1], a1, part[mf * 2 + 0][nc]));
                    part[mf * 2 + 1][nc] = fmaf(y[mf][2], a0, fmaf(y[mf][3], a1, part[mf * 2 + 1][nc]));
                }
            }
        }
        // quad reduce (sums over all 64 cols of the warp)
#pragma unroll
        for (int s = 0; s < 4; ++s)
#pragma unroll
            for (int nc = 0; nc < 10; ++nc) {
                part[s][nc] += __shfl_xor_sync(0xffffffffu, part[s][nc], 1);
                part[s][nc] += __shfl_xor_sync(0xffffffffu, part[s][nc], 2);
            }
        if ((lane & 3) == 0) {
#pragma unroll
            for (int mf = 0; mf < 2; ++mf)
#pragma unroll
                for (int h = 0; h < 2; ++h) {
                    const int row = wm * 32 + mf * 16 + h * 8 + gr;
                    float* p = &psum[((size_t)wn * 128 + row) * 12];
#pragma unroll
                    for (int nc = 0; nc < 10; ++nc) p[nc] = part[mf * 2 + h][nc];
                }
        }
        __syncthreads();

        if (t < 128) {
            const int row = t;
            const int m = m0 + row;
            const int q = m >> 5, b = m & 31;
            const size_t base = (((size_t)l * BB + b) * QQ + q) * 10;
            float val[10];
            const float* b3 = (path ? rb3 : cb3) + l * 10;
#pragma unroll
            for (int nc = 0; nc < 10; ++nc)
                val[nc] = psum[row * 12 + nc] + psum[(128 + row) * 12 + nc]
                        + psum[(256 + row) * 12 + nc] + psum[(384 + row) * 12 + nc] + b3[nc];
            if (path == 0) {
#pragma unroll
                for (int nc = 0; nc < 10; ++nc) out[base + nc] = val[nc];   // cls scores
            } else {
                const float* rp = (l == 0)
                    ? (init_ref + ((size_t)b * QQ + q) * 3)
                    : (inter_ref + (((size_t)(l - 1) * BB + b) * QQ + q) * 3);
                float r[3];
#pragma unroll
                for (int i = 0; i < 3; ++i) {
                    const float x  = fminf(fmaxf(rp[i], 0.f), 1.f);
                    const float x1 = fmaxf(x, 1e-5f);
                    const float x2 = fmaxf(1.f - x, 1e-5f);
                    r[i] = logf(x1 / x2);
                }
                const float xy0 = 1.f / (1.f + expf(-(val[0] + r[0])));
                const float xy1 = 1.f / (1.f + expf(-(val[1] + r[1])));
                const float z   = 1.f / (1.f + expf(-(val[4] + r[2])));
                float* co = out + (size_t)L6 * BB * QQ * 10 + base;
                co[0] = xy0 * 102.4f - 51.2f;
                co[1] = xy1 * 102.4f - 51.2f;
                co[2] = val[2];
                co[3] = val[3];
                co[4] = z * 8.0f - 5.0f;
                co[5] = val[5]; co[6] = val[6]; co[7] = val[7]; co[8] = val[8]; co[9] = val[9];
            }
        }
    }
}

extern "C" void kernel_launch(void* const* d_in, const int* in_sizes, int n_in,
                              void* d_out, int out_size) {
    const float* hs        = (const float*)d_in[0];
    const float* init_ref  = (const float*)d_in[1];
    const float* inter_ref = (const float*)d_in[2];
    const float* cls_w1    = (const float*)d_in[3];
    const float* cls_b1    = (const float*)d_in[4];
    const float* ln1_g     = (const float*)d_in[5];
    const float* ln1_b     = (const float*)d_in[6];
    const float* cls_w2    = (const float*)d_in[7];
    const float* cls_b2    = (const float*)d_in[8];
    const float* ln2_g     = (const float*)d_in[9];
    const float* ln2_b     = (const float*)d_in[10];
    const float* cls_w3    = (const float*)d_in[11];
    const float* cls_b3    = (const float*)d_in[12];
    const float* reg_w1    = (const float*)d_in[13];
    const float* reg_b1    = (const float*)d_in[14];
    const float* reg_w2    = (const float*)d_in[15];
    const float* reg_b2    = (const float*)d_in[16];
    const float* reg_w3    = (const float*)d_in[17];
    const float* reg_b3    = (const float*)d_in[18];
    float* out = (float*)d_out;

    cudaFuncSetAttribute(gemm_stage_kernel<0>, cudaFuncAttributeMaxDynamicSharedMemorySize, SMEM_TOTAL);
    cudaFuncSetAttribute(gemm_stage_kernel<1>, cudaFuncAttributeMaxDynamicSharedMemorySize, SMEM_TOTAL);

    split_hs_kernel<<<(int)((size_t)L6 * MM * DD / 4 / 512), 512>>>(hs);
    transpose_weights_kernel<<<dim3(8, 8, 4 * L6), dim3(32, 32)>>>(cls_w1, reg_w1, cls_w2, reg_w2);

    dim3 grid(MM / 128, 2, L6);   // 225 x {cls,reg} x 6
    gemm_stage_kernel<0><<<grid, 512, SMEM_TOTAL>>>(cls_b1, ln1_g, ln1_b, reg_b1,
                                                    cls_w3, cls_b3, reg_w3, reg_b3,
                                                    init_ref, inter_ref, out);
    gemm_stage_kernel<1><<<grid, 512, SMEM_TOTAL>>>(cls_b2, ln2_g, ln2_b, reg_b2,
                                                    cls_w3, cls_b3, reg_w3, reg_b3,
                                                    init_ref, inter_ref, out);
}

// round 8
// speedup vs baseline: 1.9519x; 1.0248x over previous
#include <cuda_runtime.h>
#include <cuda_bf16.h>
#include <math.h>
#include <stdint.h>

#define L6 6
#define BB 32
#define QQ 900
#define DD 256
#define MM (BB*QQ)                 // 28800 tokens per level
#define MD ((size_t)MM*(size_t)DD)

// ---------------- scratch (device globals; allocation-free) ----------------
__device__ __nv_bfloat16 g_ah[(size_t)L6*MM*DD];   // hs split hi
__device__ __nv_bfloat16 g_al[(size_t)L6*MM*DD];   // hs split lo
__device__ __nv_bfloat16 g_x1h[(size_t)L6*MM*DD];
__device__ __nv_bfloat16 g_x1l[(size_t)L6*MM*DD];
__device__ __nv_bfloat16 g_y1h[(size_t)L6*MM*DD];
__device__ __nv_bfloat16 g_y1l[(size_t)L6*MM*DD];
// transposed weights bf16 hi/lo: [widx][L][N=256][K=256]; widx: 0=cls_w1 1=reg_w1 2=cls_w2 3=reg_w2
__device__ __nv_bfloat16 g_wb_hi[(size_t)4*L6*DD*DD];
__device__ __nv_bfloat16 g_wb_lo[(size_t)4*L6*DD*DD];

// ---------------- helpers ----------------
__device__ __forceinline__ uint32_t smem_u32(const void* p) {
    uint32_t a;
    asm("{ .reg .u64 t; cvta.to.shared.u64 t, %1; cvt.u32.u64 %0, t; }" : "=r"(a) : "l"(p));
    return a;
}
#define CP_ASYNC16(dst, src) \
    asm volatile("cp.async.cg.shared.global [%0], [%1], 16;" :: "r"(dst), "l"(src))
#define CP_COMMIT() asm volatile("cp.async.commit_group;" ::: "memory")
#define CP_WAIT(n)  asm volatile("cp.async.wait_group %0;" :: "n"(n) : "memory")

#define LDSM4(r, addr) \
    asm volatile("ldmatrix.sync.aligned.m8n8.x4.shared.b16 {%0,%1,%2,%3}, [%4];" \
        : "=r"((r)[0]), "=r"((r)[1]), "=r"((r)[2]), "=r"((r)[3]) : "r"(addr))

__device__ __forceinline__ uint32_t pack_hi2(float x, float y, uint32_t& lo) {
    __nv_bfloat16 hx = __float2bfloat16(x), hy = __float2bfloat16(y);
    __nv_bfloat16 lx = __float2bfloat16(x - __bfloat162float(hx));
    __nv_bfloat16 ly = __float2bfloat16(y - __bfloat162float(hy));
    __nv_bfloat162 h(hx, hy), l2(lx, ly);
    lo = *reinterpret_cast<uint32_t*>(&l2);
    return *reinterpret_cast<uint32_t*>(&h);
}

__device__ __forceinline__ void mma16816(float* c, const uint32_t a[4],
                                         uint32_t b0, uint32_t b1) {
    asm volatile(
        "mma.sync.aligned.m16n8k16.row.col.f32.bf16.bf16.f32 "
        "{%0,%1,%2,%3}, {%4,%5,%6,%7}, {%8,%9}, {%0,%1,%2,%3};"
        : "+f"(c[0]), "+f"(c[1]), "+f"(c[2]), "+f"(c[3])
        : "r"(a[0]), "r"(a[1]), "r"(a[2]), "r"(a[3]), "r"(b0), "r"(b1));
}

// ---------------- pre-pass: hs fp32 -> hi/lo bf16 ----------------
__global__ __launch_bounds__(512)
void split_hs_kernel(const float* __restrict__ hs) {
    const size_t idx = (size_t)blockIdx.x * blockDim.x + threadIdx.x;  // float4 index
    const float4 f = ((const float4*)hs)[idx];
    uint32_t lo0, lo1;
    const uint32_t hi0 = pack_hi2(f.x, f.y, lo0);
    const uint32_t hi1 = pack_hi2(f.z, f.w, lo1);
    ((uint2*)g_ah)[idx] = make_uint2(hi0, hi1);
    ((uint2*)g_al)[idx] = make_uint2(lo0, lo1);
}

// ---------------- weight transpose + bf16 hi/lo split ----------------
__global__ void transpose_weights_kernel(const float* __restrict__ w0, const float* __restrict__ w1,
                                         const float* __restrict__ w2, const float* __restrict__ w3)
{
    __shared__ float sT[32][33];
    const float* srcs[4] = {w0, w1, w2, w3};
    const int z = blockIdx.z;
    const int mat = z / L6, l = z - mat * L6;
    const int k0 = blockIdx.y * 32, n0 = blockIdx.x * 32;
    const float* W = srcs[mat] + (size_t)l * DD * DD;   // [K,N] row-major
    sT[threadIdx.y][threadIdx.x] = W[(size_t)(k0 + threadIdx.y) * DD + n0 + threadIdx.x];
    __syncthreads();
    float v = sT[threadIdx.x][threadIdx.y];             // = W[k0+tx][n0+ty]
    __nv_bfloat16 hi = __float2bfloat16(v);
    __nv_bfloat16 lo = __float2bfloat16(v - __bfloat162float(hi));
    size_t o = (((size_t)mat * L6 + l) * DD + (n0 + threadIdx.y)) * DD + k0 + threadIdx.x;
    g_wb_hi[o] = hi;
    g_wb_lo[o] = lo;
}

// ---------------- HMMA GEMM stage (512 threads, cp.async + ldmatrix, fused head) ----------------
#define LDA 80
#define A_COMP 10240                // 128 rows * 80 B
#define B_COMP 20480                // 256 rows * 80 B
#define STAGE_BYTES (2*A_COMP + 2*B_COMP)   // 61440

#define OFF_BIAS   0
#define OFF_GAMMA  1024
#define OFF_BETA   2048
#define OFF_S1     3072      // 4*128*4 = 2048
#define OFF_S2     5120
#define OFF_W3     7168      // 256*12*4 = 12288
#define OFF_PSUM   19456     // 4*128*12*4 = 24576
#define OFF_TILES  44032
#define SMEM_TOTAL (OFF_TILES + 2*STAGE_BYTES)   // 166912

template<int STAGE>
__global__ __launch_bounds__(512, 1)
void gemm_stage_kernel(const float* __restrict__ bc, const float* __restrict__ gc,
                       const float* __restrict__ betac, const float* __restrict__ br,
                       const float* __restrict__ cw3, const float* __restrict__ cb3,
                       const float* __restrict__ rw3, const float* __restrict__ rb3,
                       const float* __restrict__ init_ref, const float* __restrict__ inter_ref,
                       float* __restrict__ out)
{
    extern __shared__ char smem[];
    float* biasS  = (float*)(smem + OFF_BIAS);
    float* gammaS = (float*)(smem + OFF_GAMMA);
    float* betaS  = (float*)(smem + OFF_BETA);
    float* s1buf  = (float*)(smem + OFF_S1);
    float* s2buf  = (float*)(smem + OFF_S2);
    float* W3s    = (float*)(smem + OFF_W3);     // [256][12]
    float* psum   = (float*)(smem + OFF_PSUM);   // [4][128][12]
    char*  tiles  = smem + OFF_TILES;
    const uint32_t tiles_s = smem_u32(tiles);

    const int t = threadIdx.x, lane = t & 31, wid = t >> 5;
    const int wm = wid & 3, wn = wid >> 2;       // warp tile: 32 rows x 64 cols
    const int l = blockIdx.z, path = blockIdx.y, m0 = blockIdx.x * 128;

    const int widx = STAGE * 2 + path;
    const __nv_bfloat16* Bh_g = g_wb_hi + ((size_t)widx * L6 + l) * DD * DD;
    const __nv_bfloat16* Bl_g = g_wb_lo + ((size_t)widx * L6 + l) * DD * DD;
    const __nv_bfloat16* Agh, * Agl;
    if (STAGE == 0) {
        Agh = g_ah + (size_t)l * MD + (size_t)m0 * DD;
        Agl = g_al + (size_t)l * MD + (size_t)m0 * DD;
    } else {
        Agh = (path ? g_y1h : g_x1h) + (size_t)l * MD + (size_t)m0 * DD;
        Agl = (path ? g_y1l : g_x1l) + (size_t)l * MD + (size_t)m0 * DD;
    }

    // ---- parameter loads ----
    if (t < 256) {
        biasS[t] = ((path ? br : bc) + l * DD)[t];
        if (path == 0) { gammaS[t] = gc[l * DD + t]; betaS[t] = betac[l * DD + t]; }
    }
    if (STAGE == 1) {
        const float* w3g = (path ? rw3 : cw3) + l * 2560;
        for (int idx = t; idx < 2560; idx += 512) {
            const int k = idx / 10, nc = idx - k * 10;
            W3s[k * 12 + nc] = w3g[idx];
        }
    }

    // ---- cp.async chunk loader ----
    auto load_chunk = [&](int kt, int buf) {
        const int kc = kt * 32;
        const uint32_t base = tiles_s + buf * STAGE_BYTES;
        {
            const int row = t >> 2, c = t & 3;
            const uint32_t d = base + row * LDA + c * 16;
            CP_ASYNC16(d,           Agh + (size_t)row * DD + kc + c * 8);
            CP_ASYNC16(d + A_COMP,  Agl + (size_t)row * DD + kc + c * 8);
        }
#pragma unroll
        for (int s = 0; s < 2; ++s) {
            const int idx = s * 512 + t, row = idx >> 2, c = idx & 3;
            const uint32_t d = base + 2 * A_COMP + row * LDA + c * 16;
            CP_ASYNC16(d,           Bh_g + (size_t)row * DD + kc + c * 8);
            CP_ASYNC16(d + B_COMP,  Bl_g + (size_t)row * DD + kc + c * 8);
        }
    };

    float acc[2][8][4];
#pragma unroll
    for (int mf = 0; mf < 2; ++mf)
#pragma unroll
        for (int nf = 0; nf < 8; ++nf)
#pragma unroll
            for (int i = 0; i < 4; ++i) acc[mf][nf][i] = 0.f;

    load_chunk(0, 0);
    CP_COMMIT();
    __syncthreads();   // params visible

    const int gr = lane >> 2, gc2 = (lane & 3) << 1;
    // per-lane ldmatrix row/col offsets (tile-order matches mma fragment layout)
    const uint32_t a_off = (uint32_t)(wm * 32 + (lane & 7) + ((lane >> 3) & 1) * 8) * LDA
                         + ((lane >> 4) & 1) * 16;
    const uint32_t b_off = (uint32_t)(wn * 64 + (lane & 7) + ((lane >> 4) & 1) * 8) * LDA
                         + ((lane >> 3) & 1) * 16;

#pragma unroll 1
    for (int kt = 0; kt < 8; ++kt) {
        if (kt < 7) { load_chunk(kt + 1, (kt + 1) & 1); CP_COMMIT(); CP_WAIT(1); }
        else        { CP_WAIT(0); }
        __syncthreads();
        {
            const uint32_t base = tiles_s + (kt & 1) * STAGE_BYTES;
            const uint32_t baseB = base + 2 * A_COMP;
#pragma unroll
            for (int ks = 0; ks < 2; ++ks) {
                const uint32_t kb = ks * 32;
                uint32_t ah[2][4], al[2][4];
#pragma unroll
                for (int mf = 0; mf < 2; ++mf) {
                    const uint32_t aa = base + a_off + mf * (16 * LDA) + kb;
                    LDSM4(ah[mf], aa);
                    LDSM4(al[mf], aa + A_COMP);
                }
#pragma unroll
                for (int nfp = 0; nfp < 4; ++nfp) {
                    uint32_t bh[4], bl[4];
                    const uint32_t ba = baseB + b_off + nfp * (16 * LDA) + kb;
                    LDSM4(bh, ba);
                    LDSM4(bl, ba + B_COMP);
#pragma unroll
                    for (int mf = 0; mf < 2; ++mf) {
                        mma16816(acc[mf][2 * nfp],     ah[mf], bh[0], bh[1]);   // hi*hi
                        mma16816(acc[mf][2 * nfp],     al[mf], bh[0], bh[1]);   // lo*hi
                        mma16816(acc[mf][2 * nfp],     ah[mf], bl[0], bl[1]);   // hi*lo
                        mma16816(acc[mf][2 * nfp + 1], ah[mf], bh[2], bh[3]);
                        mma16816(acc[mf][2 * nfp + 1], al[mf], bh[2], bh[3]);
                        mma16816(acc[mf][2 * nfp + 1], ah[mf], bl[2], bl[3]);
                    }
                }
            }
        }
        __syncthreads();
    }

    // ---------------- epilogue ----------------
#pragma unroll
    for (int nf = 0; nf < 8; ++nf) {
        const int cb = wn * 64 + nf * 8 + gc2;
        const float b0 = biasS[cb], b1 = biasS[cb + 1];
#pragma unroll
        for (int mf = 0; mf < 2; ++mf) {
            acc[mf][nf][0] += b0; acc[mf][nf][1] += b1;
            acc[mf][nf][2] += b0; acc[mf][nf][3] += b1;
        }
    }

    float mean_[2][2], rs_[2][2];
    if (path == 0) {
        float s1[2][2] = {{0.f,0.f},{0.f,0.f}}, s2[2][2] = {{0.f,0.f},{0.f,0.f}};
#pragma unroll
        for (int nf = 0; nf < 8; ++nf)
#pragma unroll
            for (int mf = 0; mf < 2; ++mf) {
                s1[mf][0] += acc[mf][nf][0] + acc[mf][nf][1];
                s2[mf][0] += acc[mf][nf][0]*acc[mf][nf][0] + acc[mf][nf][1]*acc[mf][nf][1];
                s1[mf][1] += acc[mf][nf][2] + acc[mf][nf][3];
                s2[mf][1] += acc[mf][nf][2]*acc[mf][nf][2] + acc[mf][nf][3]*acc[mf][nf][3];
            }
#pragma unroll
        for (int mf = 0; mf < 2; ++mf)
#pragma unroll
            for (int h = 0; h < 2; ++h) {
                s1[mf][h] += __shfl_xor_sync(0xffffffffu, s1[mf][h], 1);
                s1[mf][h] += __shfl_xor_sync(0xffffffffu, s1[mf][h], 2);
                s2[mf][h] += __shfl_xor_sync(0xffffffffu, s2[mf][h], 1);
                s2[mf][h] += __shfl_xor_sync(0xffffffffu, s2[mf][h], 2);
            }
        if ((lane & 3) == 0) {
#pragma unroll
            for (int mf = 0; mf < 2; ++mf)
#pragma unroll
                for (int h = 0; h < 2; ++h) {
                    const int row = wm * 32 + mf * 16 + h * 8 + gr;
                    s1buf[wn * 128 + row] = s1[mf][h];
                    s2buf[wn * 128 + row] = s2[mf][h];
                }
        }
        __syncthreads();
#pragma unroll
        for (int mf = 0; mf < 2; ++mf)
#pragma unroll
            for (int h = 0; h < 2; ++h) {
                const int row = wm * 32 + mf * 16 + h * 8 + gr;
                const float t1 = s1buf[row] + s1buf[128 + row] + s1buf[256 + row] + s1buf[384 + row];
                const float t2 = s2buf[row] + s2buf[128 + row] + s2buf[256 + row] + s2buf[384 + row];
                const float mean = t1 * (1.0f / 256.0f);
                const float var  = t2 * (1.0f / 256.0f) - mean * mean;
                mean_[mf][h] = mean;
                rs_[mf][h]   = rsqrtf(var + 1e-5f);
            }
    }

    if (STAGE == 0) {
        uint32_t* Ohi = (uint32_t*)((path ? g_y1h : g_x1h) + (size_t)l * MD + (size_t)m0 * DD);
        uint32_t* Olo = (uint32_t*)((path ? g_y1l : g_x1l) + (size_t)l * MD + (size_t)m0 * DD);
#pragma unroll
        for (int nf = 0; nf < 8; ++nf) {
            const int cb = wn * 64 + nf * 8 + gc2;
            float g0 = 1.f, g1 = 1.f, be0 = 0.f, be1 = 0.f;
            if (path == 0) { g0 = gammaS[cb]; g1 = gammaS[cb + 1]; be0 = betaS[cb]; be1 = betaS[cb + 1]; }
#pragma unroll
            for (int mf = 0; mf < 2; ++mf) {
                float y[4];
                if (path == 0) {
                    y[0] = (acc[mf][nf][0] - mean_[mf][0]) * rs_[mf][0] * g0 + be0;
                    y[1] = (acc[mf][nf][1] - mean_[mf][0]) * rs_[mf][0] * g1 + be1;
                    y[2] = (acc[mf][nf][2] - mean_[mf][1]) * rs_[mf][1] * g0 + be0;
                    y[3] = (acc[mf][nf][3] - mean_[mf][1]) * rs_[mf][1] * g1 + be1;
                } else {
                    y[0] = acc[mf][nf][0]; y[1] = acc[mf][nf][1];
                    y[2] = acc[mf][nf][2]; y[3] = acc[mf][nf][3];
                }
#pragma unroll
                for (int i = 0; i < 4; ++i) y[i] = fmaxf(y[i], 0.f);
                const int row0 = wm * 32 + mf * 16 + gr;
                uint32_t lo0, lo1;
                const uint32_t hi0 = pack_hi2(y[0], y[1], lo0);
                const uint32_t hi1 = pack_hi2(y[2], y[3], lo1);
                const size_t o0 = ((size_t)row0 * DD + cb) >> 1;
                const size_t o1 = ((size_t)(row0 + 8) * DD + cb) >> 1;
                Ohi[o0] = hi0; Olo[o0] = lo0;
                Ohi[o1] = hi1; Olo[o1] = lo1;
            }
        }
    } else {
        // ---- fused head ----
        float part[4][10];
#pragma unroll
        for (int s = 0; s < 4; ++s)
#pragma unroll
            for (int nc = 0; nc < 10; ++nc) part[s][nc] = 0.f;

#pragma unroll
        for (int nf = 0; nf < 8; ++nf) {
            const int cb = wn * 64 + nf * 8 + gc2;
            float g0 = 1.f, g1 = 1.f, be0 = 0.f, be1 = 0.f;
            if (path == 0) { g0 = gammaS[cb]; g1 = gammaS[cb + 1]; be0 = betaS[cb]; be1 = betaS[cb + 1]; }
            float y[2][4];
#pragma unroll
            for (int mf = 0; mf < 2; ++mf) {
                if (path == 0) {
                    y[mf][0] = (acc[mf][nf][0] - mean_[mf][0]) * rs_[mf][0] * g0 + be0;
                    y[mf][1] = (acc[mf][nf][1] - mean_[mf][0]) * rs_[mf][0] * g1 + be1;
                    y[mf][2] = (acc[mf][nf][2] - mean_[mf][1]) * rs_[mf][1] * g0 + be0;
                    y[mf][3] = (acc[mf][nf][3] - mean_[mf][1]) * rs_[mf][1] * g1 + be1;
                } else {
                    y[mf][0] = acc[mf][nf][0]; y[mf][1] = acc[mf][nf][1];
                    y[mf][2] = acc[mf][nf][2]; y[mf][3] = acc[mf][nf][3];
                }
#pragma unroll
                for (int i = 0; i < 4; ++i) y[mf][i] = fmaxf(y[mf][i], 0.f);
            }
            const float* w0 = &W3s[cb * 12];
            const float* w1 = &W3s[(cb + 1) * 12];
#pragma unroll
            for (int nc = 0; nc < 10; ++nc) {
                const float a0 = w0[nc], a1 = w1[nc];
#pragma unroll
                for (int mf = 0; mf < 2; ++mf) {
                    part[mf * 2 + 0][nc] = fmaf(y[mf][0], a0, fmaf(y[mf][1], a1, part[mf * 2 + 0][nc]));
                    part[mf * 2 + 1][nc] = fmaf(y[mf][2], a0, fmaf(y[mf][3], a1, part[mf * 2 + 1][nc]));
                }
            }
        }
#pragma unroll
        for (int s = 0; s < 4; ++s)
#pragma unroll
            for (int nc = 0; nc < 10; ++nc) {
                part[s][nc] += __shfl_xor_sync(0xffffffffu, part[s][nc], 1);
                part[s][nc] += __shfl_xor_sync(0xffffffffu, part[s][nc], 2);
            }
        if ((lane & 3) == 0) {
#pragma unroll
            for (int mf = 0; mf < 2; ++mf)
#pragma unroll
                for (int h = 0; h < 2; ++h) {
                    const int row = wm * 32 + mf * 16 + h * 8 + gr;
                    float* p = &psum[((size_t)wn * 128 + row) * 12];
#pragma unroll
                    for (int nc = 0; nc < 10; ++nc) p[nc] = part[mf * 2 + h][nc];
                }
        }
        __syncthreads();

        if (t < 128) {
            const int row = t;
            const int m = m0 + row;
            const int q = m >> 5, b = m & 31;
            const size_t base = (((size_t)l * BB + b) * QQ + q) * 10;
            float val[10];
            const float* b3 = (path ? rb3 : cb3) + l * 10;
#pragma unroll
            for (int nc = 0; nc < 10; ++nc)
                val[nc] = psum[row * 12 + nc] + psum[(128 + row) * 12 + nc]
                        + psum[(256 + row) * 12 + nc] + psum[(384 + row) * 12 + nc] + b3[nc];
            if (path == 0) {
#pragma unroll
                for (int nc = 0; nc < 10; ++nc) out[base + nc] = val[nc];   // cls scores
            } else {
                const float* rp = (l == 0)
                    ? (init_ref + ((size_t)b * QQ + q) * 3)
                    : (inter_ref + (((size_t)(l - 1) * BB + b) * QQ + q) * 3);
                float r[3];
#pragma unroll
                for (int i = 0; i < 3; ++i) {
                    const float x  = fminf(fmaxf(rp[i], 0.f), 1.f);
                    const float x1 = fmaxf(x, 1e-5f);
                    const float x2 = fmaxf(1.f - x, 1e-5f);
                    r[i] = logf(x1 / x2);
                }
                const float xy0 = 1.f / (1.f + expf(-(val[0] + r[0])));
                const float xy1 = 1.f / (1.f + expf(-(val[1] + r[1])));
                const float z   = 1.f / (1.f + expf(-(val[4] + r[2])));
                float* co = out + (size_t)L6 * BB * QQ * 10 + base;
                co[0] = xy0 * 102.4f - 51.2f;
                co[1] = xy1 * 102.4f - 51.2f;
                co[2] = val[2];
                co[3] = val[3];
                co[4] = z * 8.0f - 5.0f;
                co[5] = val[5]; co[6] = val[6]; co[7] = val[7]; co[8] = val[8]; co[9] = val[9];
            }
        }
    }
}

extern "C" void kernel_launch(void* const* d_in, const int* in_sizes, int n_in,
                              void* d_out, int out_size) {
    const float* hs        = (const float*)d_in[0];
    const float* init_ref  = (const float*)d_in[1];
    const float* inter_ref = (const float*)d_in[2];
    const float* cls_w1    = (const float*)d_in[3];
    const float* cls_b1    = (const float*)d_in[4];
    const float* ln1_g     = (const float*)d_in[5];
    const float* ln1_b     = (const float*)d_in[6];
    const float* cls_w2    = (const float*)d_in[7];
    const float* cls_b2    = (const float*)d_in[8];
    const float* ln2_g     = (const float*)d_in[9];
    const float* ln2_b     = (const float*)d_in[10];
    const float* cls_w3    = (const float*)d_in[11];
    const float* cls_b3    = (const float*)d_in[12];
    const float* reg_w1    = (const float*)d_in[13];
    const float* reg_b1    = (const float*)d_in[14];
    const float* reg_w2    = (const float*)d_in[15];
    const float* reg_b2    = (const float*)d_in[16];
    const float* reg_w3    = (const float*)d_in[17];
    const float* reg_b3    = (const float*)d_in[18];
    float* out = (float*)d_out;

    cudaFuncSetAttribute(gemm_stage_kernel<0>, cudaFuncAttributeMaxDynamicSharedMemorySize, SMEM_TOTAL);
    cudaFuncSetAttribute(gemm_stage_kernel<1>, cudaFuncAttributeMaxDynamicSharedMemorySize, SMEM_TOTAL);

    split_hs_kernel<<<(int)((size_t)L6 * MM * DD / 4 / 512), 512>>>(hs);
    transpose_weights_kernel<<<dim3(8, 8, 4 * L6), dim3(32, 32)>>>(cls_w1, reg_w1, cls_w2, reg_w2);

    dim3 grid(MM / 128, 2, L6);   // 225 x {cls,reg} x 6
    gemm_stage_kernel<0><<<grid, 512, SMEM_TOTAL>>>(cls_b1, ln1_g, ln1_b, reg_b1,
                                                    cls_w3, cls_b3, reg_w3, reg_b3,
                                                    init_ref, inter_ref, out);
    gemm_stage_kernel<1><<<grid, 512, SMEM_TOTAL>>>(cls_b2, ln2_g, ln2_b, reg_b2,
                                                    cls_w3, cls_b3, reg_w3, reg_b3,
                                                    init_ref, inter_ref, out);
}